// round 4
// baseline (speedup 1.0000x reference)
#include <cuda_runtime.h>
#include <math.h>

// Problem constants
#define BB   2
#define TT   2048
#define CC   1024
#define NH   16
#define NKV  4
#define HD   64
#define MTOT (BB*TT)          // 4096
#define QKVN 1536             // 1024 + 256 + 256

// ---------------- scratch (device globals; no allocation allowed) ----------
__device__ float g_qkv[MTOT * QKVN];          // x @ [Wq|Wk|Wv]
__device__ float g_Q[BB * NH  * TT * HD];     // [b,h,t,d] after rope+rms
__device__ float g_K[BB * NKV * TT * HD];
__device__ float g_V[BB * NKV * TT * HD];
__device__ float g_Y[MTOT * CC];              // attention output [b,t,h,d]

// ---------------- SGEMM: 128x128 block, BK=8, 8x8 per thread ---------------
__device__ __forceinline__ void sgemm_tile(
    const float* __restrict__ A, int lda,
    const float* __restrict__ B, int ldb,
    float* __restrict__ C, int ldc,
    int m0, int n0B, int n0C, int K)
{
    __shared__ float As[8][128];
    __shared__ float Bs[8][128];
    const int tid = threadIdx.x;
    const int tx = tid & 15;      // 0..15
    const int ty = tid >> 4;      // 0..15

    float acc[8][8] = {};

    const int ar = tid >> 1;          // 0..127
    const int ac = (tid & 1) * 4;     // 0 or 4
    const int br = tid >> 5;          // 0..7
    const int bc = (tid & 31) * 4;    // 0..124

    for (int k0 = 0; k0 < K; k0 += 8) {
        float4 av = *(const float4*)&A[(m0 + ar) * lda + k0 + ac];
        float4 bv = *(const float4*)&B[(k0 + br) * ldb + n0B + bc];
        As[ac + 0][ar] = av.x;
        As[ac + 1][ar] = av.y;
        As[ac + 2][ar] = av.z;
        As[ac + 3][ar] = av.w;
        *(float4*)&Bs[br][bc] = bv;
        __syncthreads();

        #pragma unroll
        for (int kk = 0; kk < 8; kk++) {
            float4 a0 = *(const float4*)&As[kk][ty * 4];
            float4 a1 = *(const float4*)&As[kk][64 + ty * 4];
            float4 b0 = *(const float4*)&Bs[kk][tx * 4];
            float4 b1 = *(const float4*)&Bs[kk][64 + tx * 4];
            float am[8] = {a0.x, a0.y, a0.z, a0.w, a1.x, a1.y, a1.z, a1.w};
            float bn[8] = {b0.x, b0.y, b0.z, b0.w, b1.x, b1.y, b1.z, b1.w};
            #pragma unroll
            for (int i = 0; i < 8; i++)
                #pragma unroll
                for (int j = 0; j < 8; j++)
                    acc[i][j] += am[i] * bn[j];
        }
        __syncthreads();
    }

    #pragma unroll
    for (int i = 0; i < 8; i++) {
        int row = m0 + ((i < 4) ? (ty * 4 + i) : (64 + ty * 4 + (i - 4)));
        float4 c0 = make_float4(acc[i][0], acc[i][1], acc[i][2], acc[i][3]);
        float4 c1 = make_float4(acc[i][4], acc[i][5], acc[i][6], acc[i][7]);
        *(float4*)&C[row * ldc + n0C + tx * 4]      = c0;
        *(float4*)&C[row * ldc + n0C + 64 + tx * 4] = c1;
    }
}

// QKV: one launch, 12 column-tiles x 32 row-tiles
__global__ void __launch_bounds__(256) qkv_gemm_kernel(
    const float* __restrict__ x,
    const float* __restrict__ Wq,
    const float* __restrict__ Wk,
    const float* __restrict__ Wv)
{
    int bx = blockIdx.x, by = blockIdx.y;
    const float* B; int ldb, n0B, n0C;
    if (bx < 8)       { B = Wq; ldb = 1024; n0B = bx * 128;        n0C = n0B; }
    else if (bx < 10) { B = Wk; ldb = 256;  n0B = (bx - 8) * 128;  n0C = 1024 + n0B; }
    else              { B = Wv; ldb = 256;  n0B = (bx - 10) * 128; n0C = 1280 + n0B; }
    sgemm_tile(x, CC, B, ldb, g_qkv, QKVN, by * 128, n0B, n0C, CC);
}

__global__ void __launch_bounds__(256) proj_gemm_kernel(
    const float* __restrict__ Wp, float* __restrict__ out)
{
    sgemm_tile(g_Y, CC, Wp, CC, out, CC,
               blockIdx.y * 128, blockIdx.x * 128, blockIdx.x * 128, CC);
}

// -------- pointwise: gate + value-embed, RoPE, RMSNorm*1.2, layout split ----
// one block per (b,t), 128 threads = 4 warps; warp w owns kv-head w and
// q-heads w, w+4, w+8, w+12. Lane d < 32 handles rope pair (d, d+32).
__global__ void __launch_bounds__(128) pointwise_kernel(
    const float* __restrict__ x,
    const float* __restrict__ ve,
    const float* __restrict__ cosb,
    const float* __restrict__ sinb,
    const float* __restrict__ Wg)
{
    const int bt   = blockIdx.x;            // 0..4095
    const int b    = bt >> 11;
    const int t    = bt & (TT - 1);
    const int tid  = threadIdx.x;
    const int w    = tid >> 5;              // warp 0..3  == kv head
    const int lane = tid & 31;

    // gate for kv head w: 3*sigmoid(x[:12] . Wg[:,w])
    float p = (lane < 12) ? x[bt * CC + lane] * Wg[lane * NKV + w] : 0.f;
    #pragma unroll
    for (int o = 16; o; o >>= 1) p += __shfl_xor_sync(0xffffffffu, p, o);
    const float gate = 3.f / (1.f + __expf(-p));

    const float c = cosb[t * 32 + lane];
    const float s = sinb[t * 32 + lane];
    const float* qkv = &g_qkv[bt * QKVN];

    // Q heads
    for (int h = w; h < NH; h += 4) {
        float x1 = qkv[h * HD + lane];
        float x2 = qkv[h * HD + 32 + lane];
        float y1 =  x1 * c + x2 * s;
        float y2 = -x1 * s + x2 * c;
        float ss = y1 * y1 + y2 * y2;
        #pragma unroll
        for (int o = 16; o; o >>= 1) ss += __shfl_xor_sync(0xffffffffu, ss, o);
        float r = rsqrtf(ss * (1.f / 64.f) + 1e-6f) * 1.2f;
        float* dst = &g_Q[((b * NH + h) * TT + t) * HD];
        dst[lane]      = y1 * r;
        dst[lane + 32] = y2 * r;
    }
    // K head w
    {
        float x1 = qkv[1024 + w * HD + lane];
        float x2 = qkv[1024 + w * HD + 32 + lane];
        float y1 =  x1 * c + x2 * s;
        float y2 = -x1 * s + x2 * c;
        float ss = y1 * y1 + y2 * y2;
        #pragma unroll
        for (int o = 16; o; o >>= 1) ss += __shfl_xor_sync(0xffffffffu, ss, o);
        float r = rsqrtf(ss * (1.f / 64.f) + 1e-6f) * 1.2f;
        float* dst = &g_K[((b * NKV + w) * TT + t) * HD];
        dst[lane]      = y1 * r;
        dst[lane + 32] = y2 * r;
    }
    // V head w (gated value-embedding added; no rope/norm)
    {
        float v1 = qkv[1280 + w * HD + lane]      + gate * ve[bt * (NKV * HD) + w * HD + lane];
        float v2 = qkv[1280 + w * HD + 32 + lane] + gate * ve[bt * (NKV * HD) + w * HD + 32 + lane];
        float* dst = &g_V[((b * NKV + w) * TT + t) * HD];
        dst[lane]      = v1;
        dst[lane + 32] = v2;
    }
}

// ---------------- flash attention, sliding window, 64x64 tiles --------------
#define PITCH 68   // 272B rows: 16B aligned for float4, odd-ish banking

__global__ void __launch_bounds__(256) attn_kernel(const void* __restrict__ winptr)
{
    extern __shared__ float sm[];
    float* Qt   = sm;                    // [64][PITCH]  Q transposed: Qt[d][r]
    float* KtPs = sm + 64 * PITCH;       // K transposed, reused as P scores
    float* Vs   = sm + 2 * 64 * PITCH;   // [64][64]
    float* m_s  = Vs + 64 * 64;          // [64]
    float* l_s  = m_s + 64;              // [64]
    float* rsc  = l_s + 64;              // [64]

    const int q0 = blockIdx.x * 64;
    const int h  = blockIdx.y;
    const int b  = blockIdx.z;
    const int kh = h >> 2;               // jnp.repeat(k, 4, axis=2)

    const int tid = threadIdx.x;
    const int tx = tid & 15, ty = tid >> 4;

    // window_size: accept int32/int64 (LE low word) or float32 encodings
    int  wi = *(const int*)winptr;
    float wf = *(const float*)winptr;
    const int W = (wi > 0 && wi < (1 << 20)) ? wi : (int)wf;

    const float* Qg = &g_Q[((b * NH + h) * TT + q0) * HD];
    for (int idx = tid; idx < 4096; idx += 256) {
        int r = idx >> 6, d = idx & 63;
        Qt[d * PITCH + r] = Qg[r * HD + d];
    }
    if (tid < 64) { m_s[tid] = -INFINITY; l_s[tid] = 0.f; }
    __syncthreads();

    float o[4][4] = {};

    int kbeg = q0 - W; if (kbeg < 0) kbeg = 0;
    const int kstart = (kbeg / 64) * 64;

    const float* Kg = &g_K[((b * NKV + kh) * TT) * HD];
    const float* Vg = &g_V[((b * NKV + kh) * TT) * HD];

    for (int k0 = kstart; k0 <= q0; k0 += 64) {
        // load K (transposed) and V tiles
        for (int idx = tid; idx < 4096; idx += 256) {
            int r = idx >> 6, d = idx & 63;
            KtPs[d * PITCH + r] = Kg[(k0 + r) * HD + d];
            Vs[r * 64 + d]      = Vg[(k0 + r) * HD + d];
        }
        __syncthreads();

        // S = Q K^T  (4x4 per thread)
        float sacc[4][4] = {};
        #pragma unroll 8
        for (int d = 0; d < 64; d++) {
            float4 qv = *(const float4*)&Qt[d * PITCH + 4 * ty];
            float4 kv = *(const float4*)&KtPs[d * PITCH + 4 * tx];
            float qa[4] = {qv.x, qv.y, qv.z, qv.w};
            float ka[4] = {kv.x, kv.y, kv.z, kv.w};
            #pragma unroll
            for (int i = 0; i < 4; i++)
                #pragma unroll
                for (int j = 0; j < 4; j++)
                    sacc[i][j] += qa[i] * ka[j];
        }
        __syncthreads();   // all K reads done before Ps overwrites the buffer

        // scale + sliding-window causal mask; write scores
        #pragma unroll
        for (int i = 0; i < 4; i++) {
            int qg = q0 + 4 * ty + i;
            float4 pv;
            {
                int kg = k0 + 4 * tx;
                pv.x = ((kg + 0 <= qg) && (qg - (kg + 0) <= W)) ? sacc[i][0] * 0.125f : -1e9f;
                pv.y = ((kg + 1 <= qg) && (qg - (kg + 1) <= W)) ? sacc[i][1] * 0.125f : -1e9f;
                pv.z = ((kg + 2 <= qg) && (qg - (kg + 2) <= W)) ? sacc[i][2] * 0.125f : -1e9f;
                pv.w = ((kg + 3 <= qg) && (qg - (kg + 3) <= W)) ? sacc[i][3] * 0.125f : -1e9f;
            }
            *(float4*)&KtPs[(4 * ty + i) * PITCH + 4 * tx] = pv;
        }
        __syncthreads();

        // online softmax: 4 threads per row (consecutive lanes)
        {
            int row = tid >> 2, q = tid & 3;
            float* pr = &KtPs[row * PITCH + q * 16];
            float mx = -INFINITY;
            #pragma unroll
            for (int cix = 0; cix < 16; cix++) mx = fmaxf(mx, pr[cix]);
            mx = fmaxf(mx, __shfl_xor_sync(0xffffffffu, mx, 1));
            mx = fmaxf(mx, __shfl_xor_sync(0xffffffffu, mx, 2));
            float mold = m_s[row];
            float mnew = fmaxf(mold, mx);
            float sum = 0.f;
            #pragma unroll
            for (int cix = 0; cix < 16; cix++) {
                float pe = __expf(pr[cix] - mnew);
                pr[cix] = pe;
                sum += pe;
            }
            sum += __shfl_xor_sync(0xffffffffu, sum, 1);
            sum += __shfl_xor_sync(0xffffffffu, sum, 2);
            if (q == 0) {
                float sc = __expf(mold - mnew);
                rsc[row] = sc;
                l_s[row] = l_s[row] * sc + sum;
                m_s[row] = mnew;
            }
        }
        __syncthreads();

        // rescale O, then O += P V
        #pragma unroll
        for (int i = 0; i < 4; i++) {
            float sc = rsc[4 * ty + i];
            #pragma unroll
            for (int j = 0; j < 4; j++) o[i][j] *= sc;
        }
        #pragma unroll 4
        for (int j = 0; j < 64; j++) {
            float4 vv = *(const float4*)&Vs[j * 64 + 4 * tx];
            float va[4] = {vv.x, vv.y, vv.z, vv.w};
            float pj[4];
            #pragma unroll
            for (int i = 0; i < 4; i++) pj[i] = KtPs[(4 * ty + i) * PITCH + j];
            #pragma unroll
            for (int i = 0; i < 4; i++)
                #pragma unroll
                for (int dd = 0; dd < 4; dd++)
                    o[i][dd] += pj[i] * va[dd];
        }
        __syncthreads();   // before next tile overwrites KtPs / Vs
    }

    // write O / l  -> g_Y laid out [b, t, h, d]
    #pragma unroll
    for (int i = 0; i < 4; i++) {
        int row = 4 * ty + i;
        float linv = 1.f / l_s[row];
        float4 ov = make_float4(o[i][0] * linv, o[i][1] * linv,
                                o[i][2] * linv, o[i][3] * linv);
        *(float4*)&g_Y[(b * TT + q0 + row) * CC + h * HD + 4 * tx] = ov;
    }
}

// ---------------------------------------------------------------------------
extern "C" void kernel_launch(void* const* d_in, const int* in_sizes, int n_in,
                              void* d_out, int out_size)
{
    const float* x    = (const float*)d_in[0];
    const float* ve   = (const float*)d_in[1];
    const float* cosb = (const float*)d_in[2];
    const float* sinb = (const float*)d_in[3];
    const float* Wq   = (const float*)d_in[4];
    const float* Wk   = (const float*)d_in[5];
    const float* Wv   = (const float*)d_in[6];
    const float* Wp   = (const float*)d_in[7];
    const float* Wg   = (const float*)d_in[8];
    const void*  win  = d_in[9];
    float* out = (float*)d_out;

    const int attn_smem = (2 * 64 * PITCH + 64 * 64 + 3 * 64) * (int)sizeof(float); // 51968
    cudaFuncSetAttribute(attn_kernel, cudaFuncAttributeMaxDynamicSharedMemorySize,
                         attn_smem);

    qkv_gemm_kernel<<<dim3(12, 32), 256>>>(x, Wq, Wk, Wv);
    pointwise_kernel<<<MTOT, 128>>>(x, ve, cosb, sinb, Wg);
    attn_kernel<<<dim3(TT / 64, NH, BB), 256, attn_smem>>>(win);
    proj_gemm_kernel<<<dim3(8, 32), 256>>>(Wp, out);
}

// round 6
// speedup vs baseline: 1.4686x; 1.4686x over previous
#include <cuda_runtime.h>
#include <cuda_bf16.h>
#include <math.h>
#include <stdint.h>

// Problem constants
#define BB   2
#define TT   2048
#define CC   1024
#define NH   16
#define NKV  4
#define HD   64
#define MTOT (BB*TT)          // 4096
#define QKVN 1536             // 1024 + 256 + 256

// ---------------- scratch (device globals; no allocation allowed) ----------
__device__ float g_qkv[MTOT * QKVN];          // x @ [Wq|Wk|Wv] (fp32)
__device__ float g_Q[BB * NH  * TT * HD];     // [b,h,t,d] after rope+rms
__device__ float g_K[BB * NKV * TT * HD];
__device__ float g_V[BB * NKV * TT * HD];
__device__ float g_Y[MTOT * CC];              // attention output [b,t,h,d]
// transposed + bf16-split weights: Wt[n][k] (K-major, K=1024)
__device__ __nv_bfloat16 g_wh[QKVN * CC];
__device__ __nv_bfloat16 g_wl[QKVN * CC];
__device__ __nv_bfloat16 g_ph[CC * CC];
__device__ __nv_bfloat16 g_pl[CC * CC];

// ---------------------------------------------------------------------------
__device__ __forceinline__ uint32_t smem_u32(const void* p) {
    uint32_t a;
    asm("{ .reg .u64 t; cvta.to.shared.u64 t, %1; cvt.u32.u64 %0, t; }"
        : "=r"(a) : "l"(p));
    return a;
}

__device__ __forceinline__ void split2(float v, __nv_bfloat16& hi, __nv_bfloat16& lo) {
    hi = __float2bfloat16(v);
    lo = __float2bfloat16(v - __bfloat162float(hi));
}

__device__ __forceinline__ void ldm_x4(uint32_t addr, uint32_t r[4]) {
    asm volatile("ldmatrix.sync.aligned.m8n8.x4.shared.b16 {%0,%1,%2,%3}, [%4];"
        : "=r"(r[0]), "=r"(r[1]), "=r"(r[2]), "=r"(r[3]) : "r"(addr));
}

__device__ __forceinline__ void mma_bf16(float d[4], const uint32_t a[4],
                                         const uint32_t b[2]) {
    asm volatile(
        "mma.sync.aligned.m16n8k16.row.col.f32.bf16.bf16.f32 "
        "{%0,%1,%2,%3}, {%4,%5,%6,%7}, {%8,%9}, {%0,%1,%2,%3};"
        : "+f"(d[0]), "+f"(d[1]), "+f"(d[2]), "+f"(d[3])
        : "r"(a[0]), "r"(a[1]), "r"(a[2]), "r"(a[3]), "r"(b[0]), "r"(b[1]));
}

// ======= weight transpose + bf16 split: dst[n0+n][k] = src[k][n] ============
__global__ void __launch_bounds__(256) wtrans_kernel(
    const float* __restrict__ src, int N, int n0out,
    __nv_bfloat16* __restrict__ dh, __nv_bfloat16* __restrict__ dl)
{
    __shared__ float t[32][33];
    const int tx = threadIdx.x & 31, ty = threadIdx.x >> 5;   // 32x8
    const int k0 = blockIdx.y * 32, nb = blockIdx.x * 32;
    #pragma unroll
    for (int i = 0; i < 4; i++)
        t[ty + 8 * i][tx] = src[(size_t)(k0 + ty + 8 * i) * N + nb + tx];
    __syncthreads();
    #pragma unroll
    for (int i = 0; i < 4; i++) {
        int nl = ty + 8 * i;
        float v = t[tx][nl];
        __nv_bfloat16 hi, lo; split2(v, hi, lo);
        size_t idx = (size_t)(n0out + nb + nl) * 1024 + k0 + tx;
        dh[idx] = hi; dl[idx] = lo;
    }
}

// ============ split-bf16 mma.sync GEMM: C[128,128] tile per CTA =============
// C[m][n] = sum_k A[m][k] * Wt[n][k]; A fp32 (split inline), B pre-split bf16.
// 8 warps: 2 (M) x 4 (N); warp tile 64x32; k-chunk 32.
#define SP 40   // smem row pitch in bf16 elems (80B) -> ldmatrix conflict-free

__global__ void __launch_bounds__(256, 2)
tc_gemm(const float* __restrict__ A,
        const __nv_bfloat16* __restrict__ Bh, const __nv_bfloat16* __restrict__ Bl,
        float* __restrict__ C, int K, int ldc)
{
    __shared__ __nv_bfloat16 sAh[128 * SP], sAl[128 * SP];
    __shared__ __nv_bfloat16 sBh[128 * SP], sBl[128 * SP];

    const int tid  = threadIdx.x;
    const int wid  = tid >> 5;
    const int lane = tid & 31;
    const int m0 = blockIdx.y * 128;
    const int n0 = blockIdx.x * 128;
    const int warp_m = wid & 1;        // 0..1
    const int warp_n = wid >> 1;       // 0..3

    float acc[4][4][4];                // [mi][nj][frag]
    #pragma unroll
    for (int i = 0; i < 4; i++)
        #pragma unroll
        for (int j = 0; j < 4; j++)
            #pragma unroll
            for (int f = 0; f < 4; f++) acc[i][j][f] = 0.f;

    const int lr = tid >> 1;           // 0..127 tile row
    const int lh = tid & 1;            // k-half (16 elems)

    const float* gA = A + (size_t)(m0 + lr) * K + lh * 16;
    const __nv_bfloat16* gbh = Bh + (size_t)(n0 + lr) * K + lh * 16;
    const __nv_bfloat16* gbl = Bl + (size_t)(n0 + lr) * K + lh * 16;
    __nv_bfloat16* wAh = &sAh[lr * SP + lh * 16];
    __nv_bfloat16* wAl = &sAl[lr * SP + lh * 16];
    __nv_bfloat16* wBh = &sBh[lr * SP + lh * 16];
    __nv_bfloat16* wBl = &sBl[lr * SP + lh * 16];

    // ldmatrix base addresses (per lane)
    const int a_row = warp_m * 64 + (lane & 15);
    const int a_koff = (lane & 16) ? 8 : 0;
    const int b_rowbase = warp_n * 32 + ((lane & 16) >> 1) + (lane & 7);
    const int b_koff = (lane & 8) ? 8 : 0;

    for (int kc = 0; kc < K; kc += 32) {
        // ---- A fp32 -> hi/lo bf16 into smem ----
        #pragma unroll
        for (int j = 0; j < 4; j++) {
            float4 v = *(const float4*)(gA + kc + j * 4);
            __align__(8) __nv_bfloat16 hb[4], lb[4];
            split2(v.x, hb[0], lb[0]); split2(v.y, hb[1], lb[1]);
            split2(v.z, hb[2], lb[2]); split2(v.w, hb[3], lb[3]);
            *(uint2*)(wAh + j * 4) = *(uint2*)hb;
            *(uint2*)(wAl + j * 4) = *(uint2*)lb;
        }
        // ---- B hi/lo bf16 into smem ----
        #pragma unroll
        for (int j = 0; j < 2; j++) {
            *(uint4*)(wBh + j * 8) = *(const uint4*)(gbh + kc + j * 8);
            *(uint4*)(wBl + j * 8) = *(const uint4*)(gbl + kc + j * 8);
        }
        __syncthreads();

        #pragma unroll
        for (int kk = 0; kk < 32; kk += 16) {
            // B fragments for this warp's 32 columns (4 n8 tiles)
            uint32_t bh[4][2], bl[4][2];
            #pragma unroll
            for (int p = 0; p < 2; p++) {
                uint32_t r[4];
                uint32_t ad = smem_u32(&sBh[(b_rowbase + p * 16) * SP + kk + b_koff]);
                ldm_x4(ad, r);
                bh[p*2][0] = r[0]; bh[p*2][1] = r[1];
                bh[p*2+1][0] = r[2]; bh[p*2+1][1] = r[3];
                ad = smem_u32(&sBl[(b_rowbase + p * 16) * SP + kk + b_koff]);
                ldm_x4(ad, r);
                bl[p*2][0] = r[0]; bl[p*2][1] = r[1];
                bl[p*2+1][0] = r[2]; bl[p*2+1][1] = r[3];
            }
            // A fragments per m16 tile, then MMAs
            #pragma unroll
            for (int mi = 0; mi < 4; mi++) {
                uint32_t ah[4], al[4];
                uint32_t ad = smem_u32(&sAh[(a_row + mi * 16) * SP + kk + a_koff]);
                ldm_x4(ad, ah);
                ad = smem_u32(&sAl[(a_row + mi * 16) * SP + kk + a_koff]);
                ldm_x4(ad, al);
                #pragma unroll
                for (int nj = 0; nj < 4; nj++) {
                    mma_bf16(acc[mi][nj], ah, bh[nj]);
                    mma_bf16(acc[mi][nj], ah, bl[nj]);
                    mma_bf16(acc[mi][nj], al, bh[nj]);
                }
            }
        }
        __syncthreads();
    }

    // ---- epilogue: fragment -> global fp32 ----
    const int gid = lane >> 2, tig = lane & 3;
    #pragma unroll
    for (int mi = 0; mi < 4; mi++) {
        int row = m0 + warp_m * 64 + mi * 16 + gid;
        #pragma unroll
        for (int nj = 0; nj < 4; nj++) {
            int col = n0 + warp_n * 32 + nj * 8 + tig * 2;
            *(float2*)&C[(size_t)row * ldc + col] =
                make_float2(acc[mi][nj][0], acc[mi][nj][1]);
            *(float2*)&C[(size_t)(row + 8) * ldc + col] =
                make_float2(acc[mi][nj][2], acc[mi][nj][3]);
        }
    }
}

// -------- pointwise: gate + value-embed, RoPE, RMSNorm*1.2, layout split ----
__global__ void __launch_bounds__(128) pointwise_kernel(
    const float* __restrict__ x,
    const float* __restrict__ ve,
    const float* __restrict__ cosb,
    const float* __restrict__ sinb,
    const float* __restrict__ Wg)
{
    const int bt   = blockIdx.x;
    const int b    = bt >> 11;
    const int t    = bt & (TT - 1);
    const int tid  = threadIdx.x;
    const int w    = tid >> 5;
    const int lane = tid & 31;

    float p = (lane < 12) ? x[bt * CC + lane] * Wg[lane * NKV + w] : 0.f;
    #pragma unroll
    for (int o = 16; o; o >>= 1) p += __shfl_xor_sync(0xffffffffu, p, o);
    const float gate = 3.f / (1.f + __expf(-p));

    const float c = cosb[t * 32 + lane];
    const float s = sinb[t * 32 + lane];
    const float* qkv = &g_qkv[bt * QKVN];

    for (int h = w; h < NH; h += 4) {
        float x1 = qkv[h * HD + lane];
        float x2 = qkv[h * HD + 32 + lane];
        float y1 =  x1 * c + x2 * s;
        float y2 = -x1 * s + x2 * c;
        float ss = y1 * y1 + y2 * y2;
        #pragma unroll
        for (int o = 16; o; o >>= 1) ss += __shfl_xor_sync(0xffffffffu, ss, o);
        float r = rsqrtf(ss * (1.f / 64.f) + 1e-6f) * 1.2f;
        float* dst = &g_Q[((b * NH + h) * TT + t) * HD];
        dst[lane]      = y1 * r;
        dst[lane + 32] = y2 * r;
    }
    {
        float x1 = qkv[1024 + w * HD + lane];
        float x2 = qkv[1024 + w * HD + 32 + lane];
        float y1 =  x1 * c + x2 * s;
        float y2 = -x1 * s + x2 * c;
        float ss = y1 * y1 + y2 * y2;
        #pragma unroll
        for (int o = 16; o; o >>= 1) ss += __shfl_xor_sync(0xffffffffu, ss, o);
        float r = rsqrtf(ss * (1.f / 64.f) + 1e-6f) * 1.2f;
        float* dst = &g_K[((b * NKV + w) * TT + t) * HD];
        dst[lane]      = y1 * r;
        dst[lane + 32] = y2 * r;
    }
    {
        float v1 = qkv[1280 + w * HD + lane]      + gate * ve[bt * (NKV * HD) + w * HD + lane];
        float v2 = qkv[1280 + w * HD + 32 + lane] + gate * ve[bt * (NKV * HD) + w * HD + 32 + lane];
        float* dst = &g_V[((b * NKV + w) * TT + t) * HD];
        dst[lane]      = v1;
        dst[lane + 32] = v2;
    }
}

// ---------------- flash attention, sliding window, 64x64 tiles --------------
#define PITCH 68

__global__ void __launch_bounds__(256) attn_kernel(const void* __restrict__ winptr)
{
    extern __shared__ float smf[];
    float* Qt   = smf;
    float* KtPs = smf + 64 * PITCH;
    float* Vs   = smf + 2 * 64 * PITCH;
    float* m_s  = Vs + 64 * 64;
    float* l_s  = m_s + 64;
    float* rsc  = l_s + 64;

    const int q0 = blockIdx.x * 64;
    const int h  = blockIdx.y;
    const int b  = blockIdx.z;
    const int kh = h >> 2;

    const int tid = threadIdx.x;
    const int tx = tid & 15, ty = tid >> 4;

    int  wi = *(const int*)winptr;
    float wf = *(const float*)winptr;
    const int W = (wi > 0 && wi < (1 << 20)) ? wi : (int)wf;

    const float* Qg = &g_Q[((b * NH + h) * TT + q0) * HD];
    for (int idx = tid; idx < 4096; idx += 256) {
        int r = idx >> 6, d = idx & 63;
        Qt[d * PITCH + r] = Qg[r * HD + d];
    }
    if (tid < 64) { m_s[tid] = -INFINITY; l_s[tid] = 0.f; }
    __syncthreads();

    float o[4][4] = {};

    int kbeg = q0 - W; if (kbeg < 0) kbeg = 0;
    const int kstart = (kbeg / 64) * 64;

    const float* Kg = &g_K[((b * NKV + kh) * TT) * HD];
    const float* Vg = &g_V[((b * NKV + kh) * TT) * HD];

    for (int k0 = kstart; k0 <= q0; k0 += 64) {
        for (int idx = tid; idx < 4096; idx += 256) {
            int r = idx >> 6, d = idx & 63;
            KtPs[d * PITCH + r] = Kg[(k0 + r) * HD + d];
            Vs[r * 64 + d]      = Vg[(k0 + r) * HD + d];
        }
        __syncthreads();

        float sacc[4][4] = {};
        #pragma unroll 8
        for (int d = 0; d < 64; d++) {
            float4 qv = *(const float4*)&Qt[d * PITCH + 4 * ty];
            float4 kv = *(const float4*)&KtPs[d * PITCH + 4 * tx];
            float qa[4] = {qv.x, qv.y, qv.z, qv.w};
            float ka[4] = {kv.x, kv.y, kv.z, kv.w};
            #pragma unroll
            for (int i = 0; i < 4; i++)
                #pragma unroll
                for (int j = 0; j < 4; j++)
                    sacc[i][j] += qa[i] * ka[j];
        }
        __syncthreads();

        #pragma unroll
        for (int i = 0; i < 4; i++) {
            int qg = q0 + 4 * ty + i;
            int kg = k0 + 4 * tx;
            float4 pv;
            pv.x = ((kg + 0 <= qg) && (qg - (kg + 0) <= W)) ? sacc[i][0] * 0.125f : -1e9f;
            pv.y = ((kg + 1 <= qg) && (qg - (kg + 1) <= W)) ? sacc[i][1] * 0.125f : -1e9f;
            pv.z = ((kg + 2 <= qg) && (qg - (kg + 2) <= W)) ? sacc[i][2] * 0.125f : -1e9f;
            pv.w = ((kg + 3 <= qg) && (qg - (kg + 3) <= W)) ? sacc[i][3] * 0.125f : -1e9f;
            *(float4*)&KtPs[(4 * ty + i) * PITCH + 4 * tx] = pv;
        }
        __syncthreads();

        {
            int row = tid >> 2, q = tid & 3;
            float* pr = &KtPs[row * PITCH + q * 16];
            float mx = -INFINITY;
            #pragma unroll
            for (int cix = 0; cix < 16; cix++) mx = fmaxf(mx, pr[cix]);
            mx = fmaxf(mx, __shfl_xor_sync(0xffffffffu, mx, 1));
            mx = fmaxf(mx, __shfl_xor_sync(0xffffffffu, mx, 2));
            float mold = m_s[row];
            float mnew = fmaxf(mold, mx);
            float sum = 0.f;
            #pragma unroll
            for (int cix = 0; cix < 16; cix++) {
                float pe = __expf(pr[cix] - mnew);
                pr[cix] = pe;
                sum += pe;
            }
            sum += __shfl_xor_sync(0xffffffffu, sum, 1);
            sum += __shfl_xor_sync(0xffffffffu, sum, 2);
            if (q == 0) {
                float sc = __expf(mold - mnew);
                rsc[row] = sc;
                l_s[row] = l_s[row] * sc + sum;
                m_s[row] = mnew;
            }
        }
        __syncthreads();

        #pragma unroll
        for (int i = 0; i < 4; i++) {
            float sc = rsc[4 * ty + i];
            #pragma unroll
            for (int j = 0; j < 4; j++) o[i][j] *= sc;
        }
        #pragma unroll 4
        for (int j = 0; j < 64; j++) {
            float4 vv = *(const float4*)&Vs[j * 64 + 4 * tx];
            float va[4] = {vv.x, vv.y, vv.z, vv.w};
            float pj[4];
            #pragma unroll
            for (int i = 0; i < 4; i++) pj[i] = KtPs[(4 * ty + i) * PITCH + j];
            #pragma unroll
            for (int i = 0; i < 4; i++)
                #pragma unroll
                for (int dd = 0; dd < 4; dd++)
                    o[i][dd] += pj[i] * va[dd];
        }
        __syncthreads();
    }

    #pragma unroll
    for (int i = 0; i < 4; i++) {
        int row = 4 * ty + i;
        float linv = 1.f / l_s[row];
        float4 ov = make_float4(o[i][0] * linv, o[i][1] * linv,
                                o[i][2] * linv, o[i][3] * linv);
        *(float4*)&g_Y[(b * TT + q0 + row) * CC + h * HD + 4 * tx] = ov;
    }
}

// ---------------------------------------------------------------------------
extern "C" void kernel_launch(void* const* d_in, const int* in_sizes, int n_in,
                              void* d_out, int out_size)
{
    const float* x    = (const float*)d_in[0];
    const float* ve   = (const float*)d_in[1];
    const float* cosb = (const float*)d_in[2];
    const float* sinb = (const float*)d_in[3];
    const float* Wq   = (const float*)d_in[4];
    const float* Wk   = (const float*)d_in[5];
    const float* Wv   = (const float*)d_in[6];
    const float* Wp   = (const float*)d_in[7];
    const float* Wg   = (const float*)d_in[8];
    const void*  win  = d_in[9];
    float* out = (float*)d_out;

    const int attn_smem = (2 * 64 * PITCH + 64 * 64 + 3 * 64) * (int)sizeof(float);
    cudaFuncSetAttribute(attn_kernel, cudaFuncAttributeMaxDynamicSharedMemorySize,
                         attn_smem);

    __nv_bfloat16 *wh, *wl, *ph, *pl;
    cudaGetSymbolAddress((void**)&wh, g_wh);
    cudaGetSymbolAddress((void**)&wl, g_wl);
    cudaGetSymbolAddress((void**)&ph, g_ph);
    cudaGetSymbolAddress((void**)&pl, g_pl);
    float *qkvp, *Yp;
    cudaGetSymbolAddress((void**)&qkvp, g_qkv);
    cudaGetSymbolAddress((void**)&Yp, g_Y);

    // weight transpose + split
    wtrans_kernel<<<dim3(32, 32), 256>>>(Wq, 1024, 0,    wh, wl);
    wtrans_kernel<<<dim3(8,  32), 256>>>(Wk, 256,  1024, wh, wl);
    wtrans_kernel<<<dim3(8,  32), 256>>>(Wv, 256,  1280, wh, wl);
    wtrans_kernel<<<dim3(32, 32), 256>>>(Wp, 1024, 0,    ph, pl);

    // qkv = x @ [Wq|Wk|Wv]  (tensor cores, split-bf16)
    tc_gemm<<<dim3(12, 32), 256>>>(x, wh, wl, qkvp, 1024, QKVN);

    pointwise_kernel<<<MTOT, 128>>>(x, ve, cosb, sinb, Wg);
    attn_kernel<<<dim3(TT / 64, NH, BB), 256, attn_smem>>>(win);

    // out = Y @ Wproj  (tensor cores, split-bf16)
    tc_gemm<<<dim3(8, 32), 256>>>(Yp, ph, pl, out, 1024, 1024);
}

// round 7
// speedup vs baseline: 2.3099x; 1.5729x over previous
#include <cuda_runtime.h>
#include <cuda_bf16.h>
#include <math.h>
#include <stdint.h>

// Problem constants
#define BB   2
#define TT   2048
#define CC   1024
#define NH   16
#define NKV  4
#define HD   64
#define MTOT (BB*TT)          // 4096
#define QKVN 1536             // 1024 + 256 + 256

// ---------------- scratch (device globals; no allocation allowed) ----------
__device__ float g_qkv[MTOT * QKVN];          // x @ [Wq|Wk|Wv] (fp32)
__device__ float g_Y[MTOT * CC];              // attention output [b,t,h,d]
// split-bf16 Q/K/V, [b,h,t,d] layout
__device__ __nv_bfloat16 g_Qh[BB * NH  * TT * HD];
__device__ __nv_bfloat16 g_Ql[BB * NH  * TT * HD];
__device__ __nv_bfloat16 g_Kh[BB * NKV * TT * HD];
__device__ __nv_bfloat16 g_Kl[BB * NKV * TT * HD];
__device__ __nv_bfloat16 g_Vh[BB * NKV * TT * HD];
__device__ __nv_bfloat16 g_Vl[BB * NKV * TT * HD];
// transposed + bf16-split weights: Wt[n][k] (K-major, K=1024)
__device__ __nv_bfloat16 g_wh[QKVN * CC];
__device__ __nv_bfloat16 g_wl[QKVN * CC];
__device__ __nv_bfloat16 g_ph[CC * CC];
__device__ __nv_bfloat16 g_pl[CC * CC];

// ---------------------------------------------------------------------------
__device__ __forceinline__ uint32_t smem_u32(const void* p) {
    uint32_t a;
    asm("{ .reg .u64 t; cvta.to.shared.u64 t, %1; cvt.u32.u64 %0, t; }"
        : "=r"(a) : "l"(p));
    return a;
}

__device__ __forceinline__ void split2(float v, __nv_bfloat16& hi, __nv_bfloat16& lo) {
    hi = __float2bfloat16(v);
    lo = __float2bfloat16(v - __bfloat162float(hi));
}

__device__ __forceinline__ void ldm_x4(uint32_t addr, uint32_t r[4]) {
    asm volatile("ldmatrix.sync.aligned.m8n8.x4.shared.b16 {%0,%1,%2,%3}, [%4];"
        : "=r"(r[0]), "=r"(r[1]), "=r"(r[2]), "=r"(r[3]) : "r"(addr));
}
__device__ __forceinline__ void ldm_x4t(uint32_t addr, uint32_t r[4]) {
    asm volatile("ldmatrix.sync.aligned.m8n8.x4.trans.shared.b16 {%0,%1,%2,%3}, [%4];"
        : "=r"(r[0]), "=r"(r[1]), "=r"(r[2]), "=r"(r[3]) : "r"(addr));
}

__device__ __forceinline__ void mma_bf16(float d[4], const uint32_t a[4],
                                         const uint32_t b[2]) {
    asm volatile(
        "mma.sync.aligned.m16n8k16.row.col.f32.bf16.bf16.f32 "
        "{%0,%1,%2,%3}, {%4,%5,%6,%7}, {%8,%9}, {%0,%1,%2,%3};"
        : "+f"(d[0]), "+f"(d[1]), "+f"(d[2]), "+f"(d[3])
        : "r"(a[0]), "r"(a[1]), "r"(a[2]), "r"(a[3]), "r"(b[0]), "r"(b[1]));
}

// pack two f32 -> bf16x2 reg (lo = e0, hi = e1)
__device__ __forceinline__ uint32_t packbf(float e0, float e1) {
    uint32_t r;
    asm("cvt.rn.bf16x2.f32 %0, %1, %2;" : "=r"(r) : "f"(e1), "f"(e0));
    return r;
}

// ======= weight transpose + bf16 split: dst[n0+n][k] = src[k][n] ============
__global__ void __launch_bounds__(256) wtrans_kernel(
    const float* __restrict__ src, int N, int n0out,
    __nv_bfloat16* __restrict__ dh, __nv_bfloat16* __restrict__ dl)
{
    __shared__ float t[32][33];
    const int tx = threadIdx.x & 31, ty = threadIdx.x >> 5;   // 32x8
    const int k0 = blockIdx.y * 32, nb = blockIdx.x * 32;
    #pragma unroll
    for (int i = 0; i < 4; i++)
        t[ty + 8 * i][tx] = src[(size_t)(k0 + ty + 8 * i) * N + nb + tx];
    __syncthreads();
    #pragma unroll
    for (int i = 0; i < 4; i++) {
        int nl = ty + 8 * i;
        float v = t[tx][nl];
        __nv_bfloat16 hi, lo; split2(v, hi, lo);
        size_t idx = (size_t)(n0out + nb + nl) * 1024 + k0 + tx;
        dh[idx] = hi; dl[idx] = lo;
    }
}

// ============ split-bf16 mma.sync GEMM: C[128,128] tile per CTA =============
#define SP 40

__global__ void __launch_bounds__(256, 2)
tc_gemm(const float* __restrict__ A,
        const __nv_bfloat16* __restrict__ Bh, const __nv_bfloat16* __restrict__ Bl,
        float* __restrict__ C, int K, int ldc)
{
    __shared__ __nv_bfloat16 sAh[128 * SP], sAl[128 * SP];
    __shared__ __nv_bfloat16 sBh[128 * SP], sBl[128 * SP];

    const int tid  = threadIdx.x;
    const int wid  = tid >> 5;
    const int lane = tid & 31;
    const int m0 = blockIdx.y * 128;
    const int n0 = blockIdx.x * 128;
    const int warp_m = wid & 1;
    const int warp_n = wid >> 1;

    float acc[4][4][4];
    #pragma unroll
    for (int i = 0; i < 4; i++)
        #pragma unroll
        for (int j = 0; j < 4; j++)
            #pragma unroll
            for (int f = 0; f < 4; f++) acc[i][j][f] = 0.f;

    const int lr = tid >> 1;
    const int lh = tid & 1;

    const float* gA = A + (size_t)(m0 + lr) * K + lh * 16;
    const __nv_bfloat16* gbh = Bh + (size_t)(n0 + lr) * K + lh * 16;
    const __nv_bfloat16* gbl = Bl + (size_t)(n0 + lr) * K + lh * 16;
    __nv_bfloat16* wAh = &sAh[lr * SP + lh * 16];
    __nv_bfloat16* wAl = &sAl[lr * SP + lh * 16];
    __nv_bfloat16* wBh = &sBh[lr * SP + lh * 16];
    __nv_bfloat16* wBl = &sBl[lr * SP + lh * 16];

    const int a_row = warp_m * 64 + (lane & 15);
    const int a_koff = (lane & 16) ? 8 : 0;
    const int b_rowbase = warp_n * 32 + ((lane & 16) >> 1) + (lane & 7);
    const int b_koff = (lane & 8) ? 8 : 0;

    for (int kc = 0; kc < K; kc += 32) {
        #pragma unroll
        for (int j = 0; j < 4; j++) {
            float4 v = *(const float4*)(gA + kc + j * 4);
            __align__(8) __nv_bfloat16 hb[4], lb[4];
            split2(v.x, hb[0], lb[0]); split2(v.y, hb[1], lb[1]);
            split2(v.z, hb[2], lb[2]); split2(v.w, hb[3], lb[3]);
            *(uint2*)(wAh + j * 4) = *(uint2*)hb;
            *(uint2*)(wAl + j * 4) = *(uint2*)lb;
        }
        #pragma unroll
        for (int j = 0; j < 2; j++) {
            *(uint4*)(wBh + j * 8) = *(const uint4*)(gbh + kc + j * 8);
            *(uint4*)(wBl + j * 8) = *(const uint4*)(gbl + kc + j * 8);
        }
        __syncthreads();

        #pragma unroll
        for (int kk = 0; kk < 32; kk += 16) {
            uint32_t bh[4][2], bl[4][2];
            #pragma unroll
            for (int p = 0; p < 2; p++) {
                uint32_t r[4];
                uint32_t ad = smem_u32(&sBh[(b_rowbase + p * 16) * SP + kk + b_koff]);
                ldm_x4(ad, r);
                bh[p*2][0] = r[0]; bh[p*2][1] = r[1];
                bh[p*2+1][0] = r[2]; bh[p*2+1][1] = r[3];
                ad = smem_u32(&sBl[(b_rowbase + p * 16) * SP + kk + b_koff]);
                ldm_x4(ad, r);
                bl[p*2][0] = r[0]; bl[p*2][1] = r[1];
                bl[p*2+1][0] = r[2]; bl[p*2+1][1] = r[3];
            }
            #pragma unroll
            for (int mi = 0; mi < 4; mi++) {
                uint32_t ah[4], al[4];
                uint32_t ad = smem_u32(&sAh[(a_row + mi * 16) * SP + kk + a_koff]);
                ldm_x4(ad, ah);
                ad = smem_u32(&sAl[(a_row + mi * 16) * SP + kk + a_koff]);
                ldm_x4(ad, al);
                #pragma unroll
                for (int nj = 0; nj < 4; nj++) {
                    mma_bf16(acc[mi][nj], ah, bh[nj]);
                    mma_bf16(acc[mi][nj], ah, bl[nj]);
                    mma_bf16(acc[mi][nj], al, bh[nj]);
                }
            }
        }
        __syncthreads();
    }

    const int gid = lane >> 2, tig = lane & 3;
    #pragma unroll
    for (int mi = 0; mi < 4; mi++) {
        int row = m0 + warp_m * 64 + mi * 16 + gid;
        #pragma unroll
        for (int nj = 0; nj < 4; nj++) {
            int col = n0 + warp_n * 32 + nj * 8 + tig * 2;
            *(float2*)&C[(size_t)row * ldc + col] =
                make_float2(acc[mi][nj][0], acc[mi][nj][1]);
            *(float2*)&C[(size_t)(row + 8) * ldc + col] =
                make_float2(acc[mi][nj][2], acc[mi][nj][3]);
        }
    }
}

// -------- pointwise: gate + ve, RoPE, RMSNorm*1.2, split-bf16 output --------
__global__ void __launch_bounds__(128) pointwise_kernel(
    const float* __restrict__ x,
    const float* __restrict__ ve,
    const float* __restrict__ cosb,
    const float* __restrict__ sinb,
    const float* __restrict__ Wg)
{
    const int bt   = blockIdx.x;
    const int b    = bt >> 11;
    const int t    = bt & (TT - 1);
    const int tid  = threadIdx.x;
    const int w    = tid >> 5;
    const int lane = tid & 31;

    float p = (lane < 12) ? x[bt * CC + lane] * Wg[lane * NKV + w] : 0.f;
    #pragma unroll
    for (int o = 16; o; o >>= 1) p += __shfl_xor_sync(0xffffffffu, p, o);
    const float gate = 3.f / (1.f + __expf(-p));

    const float c = cosb[t * 32 + lane];
    const float s = sinb[t * 32 + lane];
    const float* qkv = &g_qkv[bt * QKVN];

    for (int h = w; h < NH; h += 4) {
        float x1 = qkv[h * HD + lane];
        float x2 = qkv[h * HD + 32 + lane];
        float y1 =  x1 * c + x2 * s;
        float y2 = -x1 * s + x2 * c;
        float ss = y1 * y1 + y2 * y2;
        #pragma unroll
        for (int o = 16; o; o >>= 1) ss += __shfl_xor_sync(0xffffffffu, ss, o);
        float r = rsqrtf(ss * (1.f / 64.f) + 1e-6f) * 1.2f;
        size_t base = ((size_t)(b * NH + h) * TT + t) * HD;
        __nv_bfloat16 hi, lo;
        split2(y1 * r, hi, lo); g_Qh[base + lane]      = hi; g_Ql[base + lane]      = lo;
        split2(y2 * r, hi, lo); g_Qh[base + lane + 32] = hi; g_Ql[base + lane + 32] = lo;
    }
    {
        float x1 = qkv[1024 + w * HD + lane];
        float x2 = qkv[1024 + w * HD + 32 + lane];
        float y1 =  x1 * c + x2 * s;
        float y2 = -x1 * s + x2 * c;
        float ss = y1 * y1 + y2 * y2;
        #pragma unroll
        for (int o = 16; o; o >>= 1) ss += __shfl_xor_sync(0xffffffffu, ss, o);
        float r = rsqrtf(ss * (1.f / 64.f) + 1e-6f) * 1.2f;
        size_t base = ((size_t)(b * NKV + w) * TT + t) * HD;
        __nv_bfloat16 hi, lo;
        split2(y1 * r, hi, lo); g_Kh[base + lane]      = hi; g_Kl[base + lane]      = lo;
        split2(y2 * r, hi, lo); g_Kh[base + lane + 32] = hi; g_Kl[base + lane + 32] = lo;
    }
    {
        float v1 = qkv[1280 + w * HD + lane]      + gate * ve[bt * (NKV * HD) + w * HD + lane];
        float v2 = qkv[1280 + w * HD + 32 + lane] + gate * ve[bt * (NKV * HD) + w * HD + 32 + lane];
        size_t base = ((size_t)(b * NKV + w) * TT + t) * HD;
        __nv_bfloat16 hi, lo;
        split2(v1, hi, lo); g_Vh[base + lane]      = hi; g_Vl[base + lane]      = lo;
        split2(v2, hi, lo); g_Vh[base + lane + 32] = hi; g_Vl[base + lane + 32] = lo;
    }
}

// ======== tensor-core flash attention: 64 q-rows per CTA, 4 warps ===========
#define AP 72      // smem pitch (bf16) -> 144B rows, ldmatrix conflict-free
#define ATS (64 * AP)                    // elems per tile buffer
#define ATT_SMEM (6 * ATS * 2)           // bytes: Qh Ql Kh Kl Vh Vl

__global__ void __launch_bounds__(128) attn_tc_kernel(const void* __restrict__ winptr)
{
    extern __shared__ __nv_bfloat16 smb[];
    __nv_bfloat16* sQh = smb;
    __nv_bfloat16* sQl = smb + ATS;
    __nv_bfloat16* sKh = smb + 2 * ATS;
    __nv_bfloat16* sKl = smb + 3 * ATS;
    __nv_bfloat16* sVh = smb + 4 * ATS;
    __nv_bfloat16* sVl = smb + 5 * ATS;

    const int q0 = blockIdx.x * 64;
    const int h  = blockIdx.y;
    const int b  = blockIdx.z;
    const int kh = h >> 2;

    const int tid = threadIdx.x, w = tid >> 5, lane = tid & 31;

    int  wi = *(const int*)winptr;
    float wf = *(const float*)winptr;
    const int W = (wi > 0 && wi < (1 << 20)) ? wi : (int)wf;

    const int lr = tid >> 1, lhf = tid & 1;    // loader: row 0..63, 32-elem half

    // ---- Q tile -> smem (bf16 copy) ----
    {
        size_t gq = ((size_t)(b * NH + h) * TT + q0 + lr) * HD + lhf * 32;
        #pragma unroll
        for (int j = 0; j < 4; j++) {
            *(uint4*)&sQh[lr * AP + lhf * 32 + j * 8] = *(const uint4*)&g_Qh[gq + j * 8];
            *(uint4*)&sQl[lr * AP + lhf * 32 + j * 8] = *(const uint4*)&g_Ql[gq + j * 8];
        }
    }
    __syncthreads();

    // ---- Q fragments resident (A operand), per warp ----
    uint32_t qh[4][4], ql[4][4];
    {
        const int qrow = w * 16 + (lane & 15);
        #pragma unroll
        for (int ks = 0; ks < 4; ks++) {
            int col = ks * 16 + ((lane & 16) ? 8 : 0);
            ldm_x4(smem_u32(&sQh[qrow * AP + col]), qh[ks]);
            ldm_x4(smem_u32(&sQl[qrow * AP + col]), ql[ks]);
        }
    }

    float o[8][4];
    #pragma unroll
    for (int d = 0; d < 8; d++)
        #pragma unroll
        for (int e = 0; e < 4; e++) o[d][e] = 0.f;
    float m_lo = -INFINITY, m_hi = -INFINITY, l_lo = 0.f, l_hi = 0.f;

    const int row_lo = q0 + w * 16 + (lane >> 2);
    const int row_hi = row_lo + 8;
    const int colb   = (lane & 3) * 2;

    int kbeg = q0 - W; if (kbeg < 0) kbeg = 0;
    const int kstart = (kbeg / 64) * 64;

    const size_t kvbase = (size_t)(b * NKV + kh) * TT * HD;

    for (int k0 = kstart; k0 <= q0; k0 += 64) {
        // ---- K,V tiles -> smem ----
        {
            size_t g = kvbase + (size_t)(k0 + lr) * HD + lhf * 32;
            int so = lr * AP + lhf * 32;
            #pragma unroll
            for (int j = 0; j < 4; j++) {
                *(uint4*)&sKh[so + j * 8] = *(const uint4*)&g_Kh[g + j * 8];
                *(uint4*)&sKl[so + j * 8] = *(const uint4*)&g_Kl[g + j * 8];
                *(uint4*)&sVh[so + j * 8] = *(const uint4*)&g_Vh[g + j * 8];
                *(uint4*)&sVl[so + j * 8] = *(const uint4*)&g_Vl[g + j * 8];
            }
        }
        __syncthreads();

        // ---- S = Q K^T (split-bf16, 3 mma) ----
        float s[8][4];
        #pragma unroll
        for (int nj = 0; nj < 8; nj++)
            #pragma unroll
            for (int e = 0; e < 4; e++) s[nj][e] = 0.f;

        #pragma unroll
        for (int ks = 0; ks < 4; ks++) {
            #pragma unroll
            for (int nt = 0; nt < 4; nt++) {
                int krow = nt * 16 + ((lane & 16) >> 1) + (lane & 7);
                int col  = ks * 16 + ((lane & 8) ? 8 : 0);
                uint32_t rh[4], rl[4];
                ldm_x4(smem_u32(&sKh[krow * AP + col]), rh);
                ldm_x4(smem_u32(&sKl[krow * AP + col]), rl);
                #pragma unroll
                for (int e = 0; e < 2; e++) {
                    uint32_t bhf[2] = { rh[e*2], rh[e*2+1] };
                    uint32_t blf[2] = { rl[e*2], rl[e*2+1] };
                    mma_bf16(s[nt*2+e], qh[ks], bhf);
                    mma_bf16(s[nt*2+e], ql[ks], bhf);
                    mma_bf16(s[nt*2+e], qh[ks], blf);
                }
            }
        }

        // ---- mask + scale ----
        #pragma unroll
        for (int nj = 0; nj < 8; nj++) {
            #pragma unroll
            for (int e = 0; e < 4; e++) {
                int col = k0 + nj * 8 + colb + (e & 1);
                int row = (e < 2) ? row_lo : row_hi;
                bool ok = (col <= row) && (row - col <= W);
                s[nj][e] = ok ? s[nj][e] * 0.125f : -3e9f;
            }
        }

        // ---- online softmax (registers only) ----
        float mx_lo = -INFINITY, mx_hi = -INFINITY;
        #pragma unroll
        for (int nj = 0; nj < 8; nj++) {
            mx_lo = fmaxf(mx_lo, fmaxf(s[nj][0], s[nj][1]));
            mx_hi = fmaxf(mx_hi, fmaxf(s[nj][2], s[nj][3]));
        }
        mx_lo = fmaxf(mx_lo, __shfl_xor_sync(0xffffffffu, mx_lo, 1));
        mx_lo = fmaxf(mx_lo, __shfl_xor_sync(0xffffffffu, mx_lo, 2));
        mx_hi = fmaxf(mx_hi, __shfl_xor_sync(0xffffffffu, mx_hi, 1));
        mx_hi = fmaxf(mx_hi, __shfl_xor_sync(0xffffffffu, mx_hi, 2));

        float mnew_lo = fmaxf(fmaxf(m_lo, mx_lo), -1e9f);
        float mnew_hi = fmaxf(fmaxf(m_hi, mx_hi), -1e9f);
        float sc_lo = __expf(m_lo - mnew_lo);
        float sc_hi = __expf(m_hi - mnew_hi);
        m_lo = mnew_lo; m_hi = mnew_hi;

        float sum_lo = 0.f, sum_hi = 0.f;
        #pragma unroll
        for (int nj = 0; nj < 8; nj++) {
            s[nj][0] = __expf(s[nj][0] - mnew_lo);
            s[nj][1] = __expf(s[nj][1] - mnew_lo);
            s[nj][2] = __expf(s[nj][2] - mnew_hi);
            s[nj][3] = __expf(s[nj][3] - mnew_hi);
            sum_lo += s[nj][0] + s[nj][1];
            sum_hi += s[nj][2] + s[nj][3];
        }
        sum_lo += __shfl_xor_sync(0xffffffffu, sum_lo, 1);
        sum_lo += __shfl_xor_sync(0xffffffffu, sum_lo, 2);
        sum_hi += __shfl_xor_sync(0xffffffffu, sum_hi, 1);
        sum_hi += __shfl_xor_sync(0xffffffffu, sum_hi, 2);
        l_lo = l_lo * sc_lo + sum_lo;
        l_hi = l_hi * sc_hi + sum_hi;

        // ---- rescale O ----
        #pragma unroll
        for (int d = 0; d < 8; d++) {
            o[d][0] *= sc_lo; o[d][1] *= sc_lo;
            o[d][2] *= sc_hi; o[d][3] *= sc_hi;
        }

        // ---- P -> bf16 A-fragments (hi + residual lo) ----
        uint32_t ph[4][4], pl[4][4];
        #pragma unroll
        for (int ks = 0; ks < 4; ks++) {
            #pragma unroll
            for (int e = 0; e < 2; e++) {
                int nj = ks * 2 + e;
                float p0 = s[nj][0], p1 = s[nj][1], p2 = s[nj][2], p3 = s[nj][3];
                uint32_t h01 = packbf(p0, p1);
                uint32_t h23 = packbf(p2, p3);
                __nv_bfloat162 hb01 = *(__nv_bfloat162*)&h01;
                __nv_bfloat162 hb23 = *(__nv_bfloat162*)&h23;
                uint32_t l01 = packbf(p0 - __bfloat162float(hb01.x),
                                      p1 - __bfloat162float(hb01.y));
                uint32_t l23 = packbf(p2 - __bfloat162float(hb23.x),
                                      p3 - __bfloat162float(hb23.y));
                ph[ks][e*2]   = h01; ph[ks][e*2+1] = h23;
                pl[ks][e*2]   = l01; pl[ks][e*2+1] = l23;
            }
        }

        // ---- O += P V (V via trans ldmatrix) ----
        #pragma unroll
        for (int ks = 0; ks < 4; ks++) {
            #pragma unroll
            for (int dt = 0; dt < 4; dt++) {
                int vrow = ks * 16 + (lane & 15);
                int vcol = dt * 16 + ((lane & 16) ? 8 : 0);
                uint32_t rh[4], rl[4];
                ldm_x4t(smem_u32(&sVh[vrow * AP + vcol]), rh);
                ldm_x4t(smem_u32(&sVl[vrow * AP + vcol]), rl);
                #pragma unroll
                for (int e = 0; e < 2; e++) {
                    uint32_t bhf[2] = { rh[e*2], rh[e*2+1] };
                    uint32_t blf[2] = { rl[e*2], rl[e*2+1] };
                    mma_bf16(o[dt*2+e], ph[ks], bhf);
                    mma_bf16(o[dt*2+e], pl[ks], bhf);
                    mma_bf16(o[dt*2+e], ph[ks], blf);
                }
            }
        }
        __syncthreads();
    }

    // ---- epilogue ----
    float li_lo = 1.f / l_lo, li_hi = 1.f / l_hi;
    #pragma unroll
    for (int d = 0; d < 8; d++) {
        int col = h * HD + d * 8 + colb;
        *(float2*)&g_Y[(size_t)(b * TT + row_lo) * CC + col] =
            make_float2(o[d][0] * li_lo, o[d][1] * li_lo);
        *(float2*)&g_Y[(size_t)(b * TT + row_hi) * CC + col] =
            make_float2(o[d][2] * li_hi, o[d][3] * li_hi);
    }
}

// ---------------------------------------------------------------------------
extern "C" void kernel_launch(void* const* d_in, const int* in_sizes, int n_in,
                              void* d_out, int out_size)
{
    const float* x    = (const float*)d_in[0];
    const float* ve   = (const float*)d_in[1];
    const float* cosb = (const float*)d_in[2];
    const float* sinb = (const float*)d_in[3];
    const float* Wq   = (const float*)d_in[4];
    const float* Wk   = (const float*)d_in[5];
    const float* Wv   = (const float*)d_in[6];
    const float* Wp   = (const float*)d_in[7];
    const float* Wg   = (const float*)d_in[8];
    const void*  win  = d_in[9];
    float* out = (float*)d_out;

    cudaFuncSetAttribute(attn_tc_kernel, cudaFuncAttributeMaxDynamicSharedMemorySize,
                         ATT_SMEM);

    __nv_bfloat16 *wh, *wl, *ph, *pl;
    cudaGetSymbolAddress((void**)&wh, g_wh);
    cudaGetSymbolAddress((void**)&wl, g_wl);
    cudaGetSymbolAddress((void**)&ph, g_ph);
    cudaGetSymbolAddress((void**)&pl, g_pl);
    float *qkvp, *Yp;
    cudaGetSymbolAddress((void**)&qkvp, g_qkv);
    cudaGetSymbolAddress((void**)&Yp, g_Y);

    // weight transpose + split
    wtrans_kernel<<<dim3(32, 32), 256>>>(Wq, 1024, 0,    wh, wl);
    wtrans_kernel<<<dim3(8,  32), 256>>>(Wk, 256,  1024, wh, wl);
    wtrans_kernel<<<dim3(8,  32), 256>>>(Wv, 256,  1280, wh, wl);
    wtrans_kernel<<<dim3(32, 32), 256>>>(Wp, 1024, 0,    ph, pl);

    // qkv = x @ [Wq|Wk|Wv]
    tc_gemm<<<dim3(12, 32), 256>>>(x, wh, wl, qkvp, 1024, QKVN);

    pointwise_kernel<<<MTOT, 128>>>(x, ve, cosb, sinb, Wg);

    attn_tc_kernel<<<dim3(TT / 64, NH, BB), 128, ATT_SMEM>>>(win);

    // out = Y @ Wproj
    tc_gemm<<<dim3(8, 32), 256>>>(Yp, ph, pl, out, 1024, 1024);
}

// round 8
// speedup vs baseline: 2.4209x; 1.0480x over previous
#include <cuda_runtime.h>
#include <cuda_bf16.h>
#include <math.h>
#include <stdint.h>

// Problem constants
#define BB   2
#define TT   2048
#define CC   1024
#define NH   16
#define NKV  4
#define HD   64
#define MTOT (BB*TT)          // 4096
#define QKVN 1536             // 1024 + 256 + 256

// ---------------- scratch (device globals; no allocation allowed) ----------
__device__ float g_qkv[MTOT * QKVN];          // x @ [Wq|Wk|Wv] (fp32)
__device__ float g_Y[MTOT * CC];              // attention output [b,t,h,d]
// split-bf16 Q/K/V, [b,h,t,d] layout
__device__ __nv_bfloat16 g_Qh[BB * NH  * TT * HD];
__device__ __nv_bfloat16 g_Ql[BB * NH  * TT * HD];
__device__ __nv_bfloat16 g_Kh[BB * NKV * TT * HD];
__device__ __nv_bfloat16 g_Kl[BB * NKV * TT * HD];
__device__ __nv_bfloat16 g_Vh[BB * NKV * TT * HD];
__device__ __nv_bfloat16 g_Vl[BB * NKV * TT * HD];
// transposed + bf16-split weights: Wt[n][k] (K-major, K=1024)
__device__ __nv_bfloat16 g_wh[QKVN * CC];
__device__ __nv_bfloat16 g_wl[QKVN * CC];
__device__ __nv_bfloat16 g_ph[CC * CC];
__device__ __nv_bfloat16 g_pl[CC * CC];

// ---------------------------------------------------------------------------
__device__ __forceinline__ uint32_t smem_u32(const void* p) {
    uint32_t a;
    asm("{ .reg .u64 t; cvta.to.shared.u64 t, %1; cvt.u32.u64 %0, t; }"
        : "=r"(a) : "l"(p));
    return a;
}

__device__ __forceinline__ void split2(float v, __nv_bfloat16& hi, __nv_bfloat16& lo) {
    hi = __float2bfloat16(v);
    lo = __float2bfloat16(v - __bfloat162float(hi));
}

__device__ __forceinline__ void ldm_x4(uint32_t addr, uint32_t r[4]) {
    asm volatile("ldmatrix.sync.aligned.m8n8.x4.shared.b16 {%0,%1,%2,%3}, [%4];"
        : "=r"(r[0]), "=r"(r[1]), "=r"(r[2]), "=r"(r[3]) : "r"(addr));
}
__device__ __forceinline__ void ldm_x4t(uint32_t addr, uint32_t r[4]) {
    asm volatile("ldmatrix.sync.aligned.m8n8.x4.trans.shared.b16 {%0,%1,%2,%3}, [%4];"
        : "=r"(r[0]), "=r"(r[1]), "=r"(r[2]), "=r"(r[3]) : "r"(addr));
}

__device__ __forceinline__ void mma_bf16(float d[4], const uint32_t a[4],
                                         const uint32_t b[2]) {
    asm volatile(
        "mma.sync.aligned.m16n8k16.row.col.f32.bf16.bf16.f32 "
        "{%0,%1,%2,%3}, {%4,%5,%6,%7}, {%8,%9}, {%0,%1,%2,%3};"
        : "+f"(d[0]), "+f"(d[1]), "+f"(d[2]), "+f"(d[3])
        : "r"(a[0]), "r"(a[1]), "r"(a[2]), "r"(a[3]), "r"(b[0]), "r"(b[1]));
}

__device__ __forceinline__ uint32_t packbf(float e0, float e1) {
    uint32_t r;
    asm("cvt.rn.bf16x2.f32 %0, %1, %2;" : "=r"(r) : "f"(e1), "f"(e0));
    return r;
}

__device__ __forceinline__ void cpa16(uint32_t s, const void* g) {
    asm volatile("cp.async.cg.shared.global [%0], [%1], 16;" :: "r"(s), "l"(g));
}
#define CP_COMMIT() asm volatile("cp.async.commit_group;" ::: "memory")
#define CP_WAIT0()  asm volatile("cp.async.wait_group 0;" ::: "memory")

// ======= weight transpose + bf16 split: dst[n0+n][k] = src[k][n] ============
__global__ void __launch_bounds__(256) wtrans_kernel(
    const float* __restrict__ src, int N, int n0out,
    __nv_bfloat16* __restrict__ dh, __nv_bfloat16* __restrict__ dl)
{
    __shared__ float t[32][33];
    const int tx = threadIdx.x & 31, ty = threadIdx.x >> 5;
    const int k0 = blockIdx.y * 32, nb = blockIdx.x * 32;
    #pragma unroll
    for (int i = 0; i < 4; i++)
        t[ty + 8 * i][tx] = src[(size_t)(k0 + ty + 8 * i) * N + nb + tx];
    __syncthreads();
    #pragma unroll
    for (int i = 0; i < 4; i++) {
        int nl = ty + 8 * i;
        float v = t[tx][nl];
        __nv_bfloat16 hi, lo; split2(v, hi, lo);
        size_t idx = (size_t)(n0out + nb + nl) * 1024 + k0 + tx;
        dh[idx] = hi; dl[idx] = lo;
    }
}

// ==== split-bf16 mma.sync GEMM, double-buffered (cp.async B, reg-prefetch A)
#define SP 40
#define TS (128 * SP)                    // elems per tile array
#define GEMM_SMEM (8 * TS * 2)           // 2 buffers x 4 arrays

__global__ void __launch_bounds__(256, 2)
tc_gemm(const float* __restrict__ A,
        const __nv_bfloat16* __restrict__ Bh, const __nv_bfloat16* __restrict__ Bl,
        float* __restrict__ C, int K, int ldc)
{
    extern __shared__ __nv_bfloat16 gsm[];

    const int tid  = threadIdx.x;
    const int wid  = tid >> 5;
    const int lane = tid & 31;
    const int m0 = blockIdx.y * 128;
    const int n0 = blockIdx.x * 128;
    const int warp_m = wid & 1;
    const int warp_n = wid >> 1;

    float acc[4][4][4];
    #pragma unroll
    for (int i = 0; i < 4; i++)
        #pragma unroll
        for (int j = 0; j < 4; j++)
            #pragma unroll
            for (int f = 0; f < 4; f++) acc[i][j][f] = 0.f;

    const int lr = tid >> 1;
    const int lh = tid & 1;
    const int soff = lr * SP + lh * 16;

    const float* gA = A + (size_t)(m0 + lr) * K + lh * 16;
    const __nv_bfloat16* gbh = Bh + (size_t)(n0 + lr) * K + lh * 16;
    const __nv_bfloat16* gbl = Bl + (size_t)(n0 + lr) * K + lh * 16;

    const int a_row = warp_m * 64 + (lane & 15);
    const int a_koff = (lane & 16) ? 8 : 0;
    const int b_rowbase = warp_n * 32 + ((lane & 16) >> 1) + (lane & 7);
    const int b_koff = (lane & 8) ? 8 : 0;

    const int nb = K >> 5;

    // ---- prologue: chunk 0 into buffer 0 ----
    {
        __nv_bfloat16* bAh = gsm;             // buf0 arrays
        __nv_bfloat16* bAl = gsm + TS;
        #pragma unroll
        for (int j = 0; j < 4; j++) {
            float4 v = *(const float4*)(gA + j * 4);
            __align__(8) __nv_bfloat16 hb[4], lb[4];
            split2(v.x, hb[0], lb[0]); split2(v.y, hb[1], lb[1]);
            split2(v.z, hb[2], lb[2]); split2(v.w, hb[3], lb[3]);
            *(uint2*)(bAh + soff + j * 4) = *(uint2*)hb;
            *(uint2*)(bAl + soff + j * 4) = *(uint2*)lb;
        }
        uint32_t sbh = smem_u32(gsm + 2 * TS + soff);
        uint32_t sbl = smem_u32(gsm + 3 * TS + soff);
        cpa16(sbh,      gbh);     cpa16(sbh + 16, gbh + 8);
        cpa16(sbl,      gbl);     cpa16(sbl + 16, gbl + 8);
        CP_COMMIT();
    }
    CP_WAIT0();
    __syncthreads();

    for (int c = 0; c < nb; c++) {
        const int buf = c & 1;
        __nv_bfloat16* sAh = gsm + buf * 4 * TS;
        __nv_bfloat16* sAl = sAh + TS;
        __nv_bfloat16* sBh = sAh + 2 * TS;
        __nv_bfloat16* sBl = sAh + 3 * TS;
        __nv_bfloat16* nAh = gsm + (buf ^ 1) * 4 * TS;
        __nv_bfloat16* nAl = nAh + TS;

        // ---- prefetch chunk c+1: A -> regs (LDG in flight), B -> cp.async ----
        float4 av[4];
        const bool more = (c + 1 < nb);
        if (more) {
            const int kc = (c + 1) << 5;
            #pragma unroll
            for (int j = 0; j < 4; j++) av[j] = *(const float4*)(gA + kc + j * 4);
            uint32_t sbh = smem_u32(nAh + 2 * TS + soff);
            uint32_t sbl = smem_u32(nAh + 3 * TS + soff);
            cpa16(sbh,      gbh + kc);     cpa16(sbh + 16, gbh + kc + 8);
            cpa16(sbl,      gbl + kc);     cpa16(sbl + 16, gbl + kc + 8);
            CP_COMMIT();
        }

        // ---- compute current buffer ----
        #pragma unroll
        for (int kk = 0; kk < 32; kk += 16) {
            uint32_t bh[4][2], bl[4][2];
            #pragma unroll
            for (int p = 0; p < 2; p++) {
                uint32_t r[4];
                uint32_t ad = smem_u32(&sBh[(b_rowbase + p * 16) * SP + kk + b_koff]);
                ldm_x4(ad, r);
                bh[p*2][0] = r[0]; bh[p*2][1] = r[1];
                bh[p*2+1][0] = r[2]; bh[p*2+1][1] = r[3];
                ad = smem_u32(&sBl[(b_rowbase + p * 16) * SP + kk + b_koff]);
                ldm_x4(ad, r);
                bl[p*2][0] = r[0]; bl[p*2][1] = r[1];
                bl[p*2+1][0] = r[2]; bl[p*2+1][1] = r[3];
            }
            #pragma unroll
            for (int mi = 0; mi < 4; mi++) {
                uint32_t ah[4], al[4];
                uint32_t ad = smem_u32(&sAh[(a_row + mi * 16) * SP + kk + a_koff]);
                ldm_x4(ad, ah);
                ad = smem_u32(&sAl[(a_row + mi * 16) * SP + kk + a_koff]);
                ldm_x4(ad, al);
                #pragma unroll
                for (int nj = 0; nj < 4; nj++) {
                    mma_bf16(acc[mi][nj], ah, bh[nj]);
                    mma_bf16(acc[mi][nj], ah, bl[nj]);
                    mma_bf16(acc[mi][nj], al, bh[nj]);
                }
            }
        }

        // ---- store prefetched A into next buffer ----
        if (more) {
            #pragma unroll
            for (int j = 0; j < 4; j++) {
                __align__(8) __nv_bfloat16 hb[4], lb[4];
                split2(av[j].x, hb[0], lb[0]); split2(av[j].y, hb[1], lb[1]);
                split2(av[j].z, hb[2], lb[2]); split2(av[j].w, hb[3], lb[3]);
                *(uint2*)(nAh + soff + j * 4) = *(uint2*)hb;
                *(uint2*)(nAl + soff + j * 4) = *(uint2*)lb;
            }
        }
        CP_WAIT0();
        __syncthreads();
    }

    const int gid = lane >> 2, tig = lane & 3;
    #pragma unroll
    for (int mi = 0; mi < 4; mi++) {
        int row = m0 + warp_m * 64 + mi * 16 + gid;
        #pragma unroll
        for (int nj = 0; nj < 4; nj++) {
            int col = n0 + warp_n * 32 + nj * 8 + tig * 2;
            *(float2*)&C[(size_t)row * ldc + col] =
                make_float2(acc[mi][nj][0], acc[mi][nj][1]);
            *(float2*)&C[(size_t)(row + 8) * ldc + col] =
                make_float2(acc[mi][nj][2], acc[mi][nj][3]);
        }
    }
}

// -------- pointwise: gate + ve, RoPE, RMSNorm*1.2, split-bf16 output --------
__global__ void __launch_bounds__(128) pointwise_kernel(
    const float* __restrict__ x,
    const float* __restrict__ ve,
    const float* __restrict__ cosb,
    const float* __restrict__ sinb,
    const float* __restrict__ Wg)
{
    const int bt   = blockIdx.x;
    const int b    = bt >> 11;
    const int t    = bt & (TT - 1);
    const int tid  = threadIdx.x;
    const int w    = tid >> 5;
    const int lane = tid & 31;

    float p = (lane < 12) ? x[bt * CC + lane] * Wg[lane * NKV + w] : 0.f;
    #pragma unroll
    for (int o = 16; o; o >>= 1) p += __shfl_xor_sync(0xffffffffu, p, o);
    const float gate = 3.f / (1.f + __expf(-p));

    const float c = cosb[t * 32 + lane];
    const float s = sinb[t * 32 + lane];
    const float* qkv = &g_qkv[bt * QKVN];

    for (int h = w; h < NH; h += 4) {
        float x1 = qkv[h * HD + lane];
        float x2 = qkv[h * HD + 32 + lane];
        float y1 =  x1 * c + x2 * s;
        float y2 = -x1 * s + x2 * c;
        float ss = y1 * y1 + y2 * y2;
        #pragma unroll
        for (int o = 16; o; o >>= 1) ss += __shfl_xor_sync(0xffffffffu, ss, o);
        float r = rsqrtf(ss * (1.f / 64.f) + 1e-6f) * 1.2f;
        size_t base = ((size_t)(b * NH + h) * TT + t) * HD;
        __nv_bfloat16 hi, lo;
        split2(y1 * r, hi, lo); g_Qh[base + lane]      = hi; g_Ql[base + lane]      = lo;
        split2(y2 * r, hi, lo); g_Qh[base + lane + 32] = hi; g_Ql[base + lane + 32] = lo;
    }
    {
        float x1 = qkv[1024 + w * HD + lane];
        float x2 = qkv[1024 + w * HD + 32 + lane];
        float y1 =  x1 * c + x2 * s;
        float y2 = -x1 * s + x2 * c;
        float ss = y1 * y1 + y2 * y2;
        #pragma unroll
        for (int o = 16; o; o >>= 1) ss += __shfl_xor_sync(0xffffffffu, ss, o);
        float r = rsqrtf(ss * (1.f / 64.f) + 1e-6f) * 1.2f;
        size_t base = ((size_t)(b * NKV + w) * TT + t) * HD;
        __nv_bfloat16 hi, lo;
        split2(y1 * r, hi, lo); g_Kh[base + lane]      = hi; g_Kl[base + lane]      = lo;
        split2(y2 * r, hi, lo); g_Kh[base + lane + 32] = hi; g_Kl[base + lane + 32] = lo;
    }
    {
        float v1 = qkv[1280 + w * HD + lane]      + gate * ve[bt * (NKV * HD) + w * HD + lane];
        float v2 = qkv[1280 + w * HD + 32 + lane] + gate * ve[bt * (NKV * HD) + w * HD + 32 + lane];
        size_t base = ((size_t)(b * NKV + w) * TT + t) * HD;
        __nv_bfloat16 hi, lo;
        split2(v1, hi, lo); g_Vh[base + lane]      = hi; g_Vl[base + lane]      = lo;
        split2(v2, hi, lo); g_Vh[base + lane + 32] = hi; g_Vl[base + lane + 32] = lo;
    }
}

// ======== tensor-core flash attention, double-buffered K/V ==================
#define AP 72
#define ATS (64 * AP)
#define ATT_SMEM ((2 + 8) * ATS * 2)     // Qh Ql + 2 x (Kh Kl Vh Vl)

__global__ void __launch_bounds__(128) attn_tc_kernel(const void* __restrict__ winptr)
{
    extern __shared__ __nv_bfloat16 smb[];
    __nv_bfloat16* sQh = smb;
    __nv_bfloat16* sQl = smb + ATS;

    const int q0 = blockIdx.x * 64;
    const int h  = blockIdx.y;
    const int b  = blockIdx.z;
    const int kh = h >> 2;

    const int tid = threadIdx.x, w = tid >> 5, lane = tid & 31;

    int  wi = *(const int*)winptr;
    float wf = *(const float*)winptr;
    const int W = (wi > 0 && wi < (1 << 20)) ? wi : (int)wf;

    const int lr = tid >> 1, lhf = tid & 1;
    const size_t kvbase = (size_t)(b * NKV + kh) * TT * HD;
    const uint32_t soff = (uint32_t)(lr * AP + lhf * 32) * 2;   // bytes in tile

    int kbeg = q0 - W; if (kbeg < 0) kbeg = 0;
    const int kstart = (kbeg / 64) * 64;

    // issue cp.async for one K/V tile into buffer bf
    auto issue_tile = [&](int k0, int bf) {
        const __nv_bfloat16* srcs[4] = {
            g_Kh + kvbase + (size_t)(k0 + lr) * HD + lhf * 32,
            g_Kl + kvbase + (size_t)(k0 + lr) * HD + lhf * 32,
            g_Vh + kvbase + (size_t)(k0 + lr) * HD + lhf * 32,
            g_Vl + kvbase + (size_t)(k0 + lr) * HD + lhf * 32 };
        uint32_t base = smem_u32(smb + 2 * ATS + bf * 4 * ATS) + soff;
        #pragma unroll
        for (int a = 0; a < 4; a++) {
            #pragma unroll
            for (int j = 0; j < 4; j++)
                cpa16(base + a * ATS * 2 + j * 16, srcs[a] + j * 8);
        }
    };

    // ---- Q tile -> smem; start pipeline ----
    {
        size_t gq = ((size_t)(b * NH + h) * TT + q0 + lr) * HD + lhf * 32;
        #pragma unroll
        for (int j = 0; j < 4; j++) {
            *(uint4*)&sQh[lr * AP + lhf * 32 + j * 8] = *(const uint4*)&g_Qh[gq + j * 8];
            *(uint4*)&sQl[lr * AP + lhf * 32 + j * 8] = *(const uint4*)&g_Ql[gq + j * 8];
        }
    }
    issue_tile(kstart, 0);
    CP_COMMIT();
    __syncthreads();

    // ---- Q fragments resident ----
    uint32_t qh[4][4], ql[4][4];
    {
        const int qrow = w * 16 + (lane & 15);
        #pragma unroll
        for (int ks = 0; ks < 4; ks++) {
            int col = ks * 16 + ((lane & 16) ? 8 : 0);
            ldm_x4(smem_u32(&sQh[qrow * AP + col]), qh[ks]);
            ldm_x4(smem_u32(&sQl[qrow * AP + col]), ql[ks]);
        }
    }

    float o[8][4];
    #pragma unroll
    for (int d = 0; d < 8; d++)
        #pragma unroll
        for (int e = 0; e < 4; e++) o[d][e] = 0.f;
    float m_lo = -INFINITY, m_hi = -INFINITY, l_lo = 0.f, l_hi = 0.f;

    const int row_lo = q0 + w * 16 + (lane >> 2);
    const int row_hi = row_lo + 8;
    const int colb   = (lane & 3) * 2;

    int buf = 0;
    for (int k0 = kstart; k0 <= q0; k0 += 64) {
        CP_WAIT0();
        __syncthreads();
        if (k0 + 64 <= q0) {
            issue_tile(k0 + 64, buf ^ 1);
            CP_COMMIT();
        }
        __nv_bfloat16* sKh = smb + 2 * ATS + buf * 4 * ATS;
        __nv_bfloat16* sKl = sKh + ATS;
        __nv_bfloat16* sVh = sKh + 2 * ATS;
        __nv_bfloat16* sVl = sKh + 3 * ATS;

        // ---- S = Q K^T ----
        float s[8][4];
        #pragma unroll
        for (int nj = 0; nj < 8; nj++)
            #pragma unroll
            for (int e = 0; e < 4; e++) s[nj][e] = 0.f;

        #pragma unroll
        for (int ks = 0; ks < 4; ks++) {
            #pragma unroll
            for (int nt = 0; nt < 4; nt++) {
                int krow = nt * 16 + ((lane & 16) >> 1) + (lane & 7);
                int col  = ks * 16 + ((lane & 8) ? 8 : 0);
                uint32_t rh[4], rl[4];
                ldm_x4(smem_u32(&sKh[krow * AP + col]), rh);
                ldm_x4(smem_u32(&sKl[krow * AP + col]), rl);
                #pragma unroll
                for (int e = 0; e < 2; e++) {
                    uint32_t bhf[2] = { rh[e*2], rh[e*2+1] };
                    uint32_t blf[2] = { rl[e*2], rl[e*2+1] };
                    mma_bf16(s[nt*2+e], qh[ks], bhf);
                    mma_bf16(s[nt*2+e], ql[ks], bhf);
                    mma_bf16(s[nt*2+e], qh[ks], blf);
                }
            }
        }

        // ---- mask + scale ----
        #pragma unroll
        for (int nj = 0; nj < 8; nj++) {
            #pragma unroll
            for (int e = 0; e < 4; e++) {
                int col = k0 + nj * 8 + colb + (e & 1);
                int row = (e < 2) ? row_lo : row_hi;
                bool ok = (col <= row) && (row - col <= W);
                s[nj][e] = ok ? s[nj][e] * 0.125f : -3e9f;
            }
        }

        // ---- online softmax ----
        float mx_lo = -INFINITY, mx_hi = -INFINITY;
        #pragma unroll
        for (int nj = 0; nj < 8; nj++) {
            mx_lo = fmaxf(mx_lo, fmaxf(s[nj][0], s[nj][1]));
            mx_hi = fmaxf(mx_hi, fmaxf(s[nj][2], s[nj][3]));
        }
        mx_lo = fmaxf(mx_lo, __shfl_xor_sync(0xffffffffu, mx_lo, 1));
        mx_lo = fmaxf(mx_lo, __shfl_xor_sync(0xffffffffu, mx_lo, 2));
        mx_hi = fmaxf(mx_hi, __shfl_xor_sync(0xffffffffu, mx_hi, 1));
        mx_hi = fmaxf(mx_hi, __shfl_xor_sync(0xffffffffu, mx_hi, 2));

        float mnew_lo = fmaxf(fmaxf(m_lo, mx_lo), -1e9f);
        float mnew_hi = fmaxf(fmaxf(m_hi, mx_hi), -1e9f);
        float sc_lo = __expf(m_lo - mnew_lo);
        float sc_hi = __expf(m_hi - mnew_hi);
        m_lo = mnew_lo; m_hi = mnew_hi;

        float sum_lo = 0.f, sum_hi = 0.f;
        #pragma unroll
        for (int nj = 0; nj < 8; nj++) {
            s[nj][0] = __expf(s[nj][0] - mnew_lo);
            s[nj][1] = __expf(s[nj][1] - mnew_lo);
            s[nj][2] = __expf(s[nj][2] - mnew_hi);
            s[nj][3] = __expf(s[nj][3] - mnew_hi);
            sum_lo += s[nj][0] + s[nj][1];
            sum_hi += s[nj][2] + s[nj][3];
        }
        sum_lo += __shfl_xor_sync(0xffffffffu, sum_lo, 1);
        sum_lo += __shfl_xor_sync(0xffffffffu, sum_lo, 2);
        sum_hi += __shfl_xor_sync(0xffffffffu, sum_hi, 1);
        sum_hi += __shfl_xor_sync(0xffffffffu, sum_hi, 2);
        l_lo = l_lo * sc_lo + sum_lo;
        l_hi = l_hi * sc_hi + sum_hi;

        #pragma unroll
        for (int d = 0; d < 8; d++) {
            o[d][0] *= sc_lo; o[d][1] *= sc_lo;
            o[d][2] *= sc_hi; o[d][3] *= sc_hi;
        }

        // ---- P -> bf16 fragments (hi + residual lo) ----
        uint32_t ph[4][4], pl[4][4];
        #pragma unroll
        for (int ks = 0; ks < 4; ks++) {
            #pragma unroll
            for (int e = 0; e < 2; e++) {
                int nj = ks * 2 + e;
                float p0 = s[nj][0], p1 = s[nj][1], p2 = s[nj][2], p3 = s[nj][3];
                uint32_t h01 = packbf(p0, p1);
                uint32_t h23 = packbf(p2, p3);
                __nv_bfloat162 hb01 = *(__nv_bfloat162*)&h01;
                __nv_bfloat162 hb23 = *(__nv_bfloat162*)&h23;
                uint32_t l01 = packbf(p0 - __bfloat162float(hb01.x),
                                      p1 - __bfloat162float(hb01.y));
                uint32_t l23 = packbf(p2 - __bfloat162float(hb23.x),
                                      p3 - __bfloat162float(hb23.y));
                ph[ks][e*2]   = h01; ph[ks][e*2+1] = h23;
                pl[ks][e*2]   = l01; pl[ks][e*2+1] = l23;
            }
        }

        // ---- O += P V ----
        #pragma unroll
        for (int ks = 0; ks < 4; ks++) {
            #pragma unroll
            for (int dt = 0; dt < 4; dt++) {
                int vrow = ks * 16 + (lane & 15);
                int vcol = dt * 16 + ((lane & 16) ? 8 : 0);
                uint32_t rh[4], rl[4];
                ldm_x4t(smem_u32(&sVh[vrow * AP + vcol]), rh);
                ldm_x4t(smem_u32(&sVl[vrow * AP + vcol]), rl);
                #pragma unroll
                for (int e = 0; e < 2; e++) {
                    uint32_t bhf[2] = { rh[e*2], rh[e*2+1] };
                    uint32_t blf[2] = { rl[e*2], rl[e*2+1] };
                    mma_bf16(o[dt*2+e], ph[ks], bhf);
                    mma_bf16(o[dt*2+e], pl[ks], bhf);
                    mma_bf16(o[dt*2+e], ph[ks], blf);
                }
            }
        }
        buf ^= 1;
    }

    float li_lo = 1.f / l_lo, li_hi = 1.f / l_hi;
    #pragma unroll
    for (int d = 0; d < 8; d++) {
        int col = h * HD + d * 8 + colb;
        *(float2*)&g_Y[(size_t)(b * TT + row_lo) * CC + col] =
            make_float2(o[d][0] * li_lo, o[d][1] * li_lo);
        *(float2*)&g_Y[(size_t)(b * TT + row_hi) * CC + col] =
            make_float2(o[d][2] * li_hi, o[d][3] * li_hi);
    }
}

// ---------------------------------------------------------------------------
extern "C" void kernel_launch(void* const* d_in, const int* in_sizes, int n_in,
                              void* d_out, int out_size)
{
    const float* x    = (const float*)d_in[0];
    const float* ve   = (const float*)d_in[1];
    const float* cosb = (const float*)d_in[2];
    const float* sinb = (const float*)d_in[3];
    const float* Wq   = (const float*)d_in[4];
    const float* Wk   = (const float*)d_in[5];
    const float* Wv   = (const float*)d_in[6];
    const float* Wp   = (const float*)d_in[7];
    const float* Wg   = (const float*)d_in[8];
    const void*  win  = d_in[9];
    float* out = (float*)d_out;

    cudaFuncSetAttribute(attn_tc_kernel, cudaFuncAttributeMaxDynamicSharedMemorySize,
                         ATT_SMEM);
    cudaFuncSetAttribute(tc_gemm, cudaFuncAttributeMaxDynamicSharedMemorySize,
                         GEMM_SMEM);

    __nv_bfloat16 *wh, *wl, *ph, *pl;
    cudaGetSymbolAddress((void**)&wh, g_wh);
    cudaGetSymbolAddress((void**)&wl, g_wl);
    cudaGetSymbolAddress((void**)&ph, g_ph);
    cudaGetSymbolAddress((void**)&pl, g_pl);
    float *qkvp, *Yp;
    cudaGetSymbolAddress((void**)&qkvp, g_qkv);
    cudaGetSymbolAddress((void**)&Yp, g_Y);

    // weight transpose + split
    wtrans_kernel<<<dim3(32, 32), 256>>>(Wq, 1024, 0,    wh, wl);
    wtrans_kernel<<<dim3(8,  32), 256>>>(Wk, 256,  1024, wh, wl);
    wtrans_kernel<<<dim3(8,  32), 256>>>(Wv, 256,  1280, wh, wl);
    wtrans_kernel<<<dim3(32, 32), 256>>>(Wp, 1024, 0,    ph, pl);

    // qkv = x @ [Wq|Wk|Wv]
    tc_gemm<<<dim3(12, 32), 256, GEMM_SMEM>>>(x, wh, wl, qkvp, 1024, QKVN);

    pointwise_kernel<<<MTOT, 128>>>(x, ve, cosb, sinb, Wg);

    attn_tc_kernel<<<dim3(TT / 64, NH, BB), 128, ATT_SMEM>>>(win);

    // out = Y @ Wproj
    tc_gemm<<<dim3(8, 32), 256, GEMM_SMEM>>>(Yp, ph, pl, out, 1024, 1024);
}

// round 10
// speedup vs baseline: 2.5903x; 1.0700x over previous
#include <cuda_runtime.h>
#include <cuda_bf16.h>
#include <math.h>
#include <stdint.h>

// Problem constants
#define BB   2
#define TT   2048
#define CC   1024
#define NH   16
#define NKV  4
#define HD   64
#define MTOT (BB*TT)          // 4096
#define QKVN 1536             // 1024 + 256 + 256

// ---------------- scratch (device globals; no allocation allowed) ----------
__device__ float g_qkv[MTOT * QKVN];          // x @ [Wq|Wk|Wv] (fp32)
__device__ float g_Y[MTOT * CC];              // attention output [b,t,h,d]
// split-bf16 Q/K/V, [b,h,t,d] layout
__device__ __nv_bfloat16 g_Qh[BB * NH  * TT * HD];
__device__ __nv_bfloat16 g_Ql[BB * NH  * TT * HD];
__device__ __nv_bfloat16 g_Kh[BB * NKV * TT * HD];
__device__ __nv_bfloat16 g_Kl[BB * NKV * TT * HD];
__device__ __nv_bfloat16 g_Vh[BB * NKV * TT * HD];
__device__ __nv_bfloat16 g_Vl[BB * NKV * TT * HD];
// transposed + bf16-split weights: Wt[n][k] (K-major, K=1024)
__device__ __nv_bfloat16 g_wh[QKVN * CC];
__device__ __nv_bfloat16 g_wl[QKVN * CC];
__device__ __nv_bfloat16 g_ph[CC * CC];
__device__ __nv_bfloat16 g_pl[CC * CC];

// ---------------------------------------------------------------------------
__device__ __forceinline__ uint32_t smem_u32(const void* p) {
    uint32_t a;
    asm("{ .reg .u64 t; cvta.to.shared.u64 t, %1; cvt.u32.u64 %0, t; }"
        : "=r"(a) : "l"(p));
    return a;
}

__device__ __forceinline__ void split2(float v, __nv_bfloat16& hi, __nv_bfloat16& lo) {
    hi = __float2bfloat16(v);
    lo = __float2bfloat16(v - __bfloat162float(hi));
}

__device__ __forceinline__ void ldm_x4(uint32_t addr, uint32_t r[4]) {
    asm volatile("ldmatrix.sync.aligned.m8n8.x4.shared.b16 {%0,%1,%2,%3}, [%4];"
        : "=r"(r[0]), "=r"(r[1]), "=r"(r[2]), "=r"(r[3]) : "r"(addr));
}
__device__ __forceinline__ void ldm_x4t(uint32_t addr, uint32_t r[4]) {
    asm volatile("ldmatrix.sync.aligned.m8n8.x4.trans.shared.b16 {%0,%1,%2,%3}, [%4];"
        : "=r"(r[0]), "=r"(r[1]), "=r"(r[2]), "=r"(r[3]) : "r"(addr));
}

__device__ __forceinline__ void mma_bf16(float d[4], const uint32_t a[4],
                                         const uint32_t b[2]) {
    asm volatile(
        "mma.sync.aligned.m16n8k16.row.col.f32.bf16.bf16.f32 "
        "{%0,%1,%2,%3}, {%4,%5,%6,%7}, {%8,%9}, {%0,%1,%2,%3};"
        : "+f"(d[0]), "+f"(d[1]), "+f"(d[2]), "+f"(d[3])
        : "r"(a[0]), "r"(a[1]), "r"(a[2]), "r"(a[3]), "r"(b[0]), "r"(b[1]));
}

__device__ __forceinline__ uint32_t packbf(float e0, float e1) {
    uint32_t r;
    asm("cvt.rn.bf16x2.f32 %0, %1, %2;" : "=r"(r) : "f"(e1), "f"(e0));
    return r;
}

__device__ __forceinline__ void cpa16(uint32_t s, const void* g) {
    asm volatile("cp.async.cg.shared.global [%0], [%1], 16;" :: "r"(s), "l"(g));
}
#define CP_COMMIT() asm volatile("cp.async.commit_group;" ::: "memory")
#define CP_WAIT0()  asm volatile("cp.async.wait_group 0;" ::: "memory")

// ======= weight transpose + bf16 split: dst[n0+n][k] = src[k][n] ============
__global__ void __launch_bounds__(256) wtrans_kernel(
    const float* __restrict__ src, int N, int n0out,
    __nv_bfloat16* __restrict__ dh, __nv_bfloat16* __restrict__ dl)
{
    __shared__ float t[32][33];
    const int tx = threadIdx.x & 31, ty = threadIdx.x >> 5;
    const int k0 = blockIdx.y * 32, nb = blockIdx.x * 32;
    #pragma unroll
    for (int i = 0; i < 4; i++)
        t[ty + 8 * i][tx] = src[(size_t)(k0 + ty + 8 * i) * N + nb + tx];
    __syncthreads();
    #pragma unroll
    for (int i = 0; i < 4; i++) {
        int nl = ty + 8 * i;
        float v = t[tx][nl];
        __nv_bfloat16 hi, lo; split2(v, hi, lo);
        size_t idx = (size_t)(n0out + nb + nl) * 1024 + k0 + tx;
        dh[idx] = hi; dl[idx] = lo;
    }
}

// ==== split-bf16 mma.sync GEMM, double-buffered (cp.async B, reg-prefetch A)
#define SP 40
#define TS (128 * SP)
#define GEMM_SMEM (8 * TS * 2)

__global__ void __launch_bounds__(256, 2)
tc_gemm(const float* __restrict__ A,
        const __nv_bfloat16* __restrict__ Bh, const __nv_bfloat16* __restrict__ Bl,
        float* __restrict__ C, int K, int ldc)
{
    extern __shared__ __nv_bfloat16 gsm[];

    const int tid  = threadIdx.x;
    const int wid  = tid >> 5;
    const int lane = tid & 31;
    const int m0 = blockIdx.y * 128;
    const int n0 = blockIdx.x * 128;
    const int warp_m = wid & 1;
    const int warp_n = wid >> 1;

    float acc[4][4][4];
    #pragma unroll
    for (int i = 0; i < 4; i++)
        #pragma unroll
        for (int j = 0; j < 4; j++)
            #pragma unroll
            for (int f = 0; f < 4; f++) acc[i][j][f] = 0.f;

    const int lr = tid >> 1;
    const int lh = tid & 1;
    const int soff = lr * SP + lh * 16;

    const float* gA = A + (size_t)(m0 + lr) * K + lh * 16;
    const __nv_bfloat16* gbh = Bh + (size_t)(n0 + lr) * K + lh * 16;
    const __nv_bfloat16* gbl = Bl + (size_t)(n0 + lr) * K + lh * 16;

    const int a_row = warp_m * 64 + (lane & 15);
    const int a_koff = (lane & 16) ? 8 : 0;
    const int b_rowbase = warp_n * 32 + ((lane & 16) >> 1) + (lane & 7);
    const int b_koff = (lane & 8) ? 8 : 0;

    const int nb = K >> 5;

    {
        __nv_bfloat16* bAh = gsm;
        __nv_bfloat16* bAl = gsm + TS;
        #pragma unroll
        for (int j = 0; j < 4; j++) {
            float4 v = *(const float4*)(gA + j * 4);
            __align__(8) __nv_bfloat16 hb[4], lb[4];
            split2(v.x, hb[0], lb[0]); split2(v.y, hb[1], lb[1]);
            split2(v.z, hb[2], lb[2]); split2(v.w, hb[3], lb[3]);
            *(uint2*)(bAh + soff + j * 4) = *(uint2*)hb;
            *(uint2*)(bAl + soff + j * 4) = *(uint2*)lb;
        }
        uint32_t sbh = smem_u32(gsm + 2 * TS + soff);
        uint32_t sbl = smem_u32(gsm + 3 * TS + soff);
        cpa16(sbh,      gbh);     cpa16(sbh + 16, gbh + 8);
        cpa16(sbl,      gbl);     cpa16(sbl + 16, gbl + 8);
        CP_COMMIT();
    }
    CP_WAIT0();
    __syncthreads();

    for (int c = 0; c < nb; c++) {
        const int buf = c & 1;
        __nv_bfloat16* sAh = gsm + buf * 4 * TS;
        __nv_bfloat16* sAl = sAh + TS;
        __nv_bfloat16* sBh = sAh + 2 * TS;
        __nv_bfloat16* sBl = sAh + 3 * TS;
        __nv_bfloat16* nAh = gsm + (buf ^ 1) * 4 * TS;
        __nv_bfloat16* nAl = nAh + TS;

        float4 av[4];
        const bool more = (c + 1 < nb);
        if (more) {
            const int kc = (c + 1) << 5;
            #pragma unroll
            for (int j = 0; j < 4; j++) av[j] = *(const float4*)(gA + kc + j * 4);
            uint32_t sbh = smem_u32(nAh + 2 * TS + soff);
            uint32_t sbl = smem_u32(nAh + 3 * TS + soff);
            cpa16(sbh,      gbh + kc);     cpa16(sbh + 16, gbh + kc + 8);
            cpa16(sbl,      gbl + kc);     cpa16(sbl + 16, gbl + kc + 8);
            CP_COMMIT();
        }

        #pragma unroll
        for (int kk = 0; kk < 32; kk += 16) {
            uint32_t bh[4][2], bl[4][2];
            #pragma unroll
            for (int p = 0; p < 2; p++) {
                uint32_t r[4];
                uint32_t ad = smem_u32(&sBh[(b_rowbase + p * 16) * SP + kk + b_koff]);
                ldm_x4(ad, r);
                bh[p*2][0] = r[0]; bh[p*2][1] = r[1];
                bh[p*2+1][0] = r[2]; bh[p*2+1][1] = r[3];
                ad = smem_u32(&sBl[(b_rowbase + p * 16) * SP + kk + b_koff]);
                ldm_x4(ad, r);
                bl[p*2][0] = r[0]; bl[p*2][1] = r[1];
                bl[p*2+1][0] = r[2]; bl[p*2+1][1] = r[3];
            }
            #pragma unroll
            for (int mi = 0; mi < 4; mi++) {
                uint32_t ah[4], al[4];
                uint32_t ad = smem_u32(&sAh[(a_row + mi * 16) * SP + kk + a_koff]);
                ldm_x4(ad, ah);
                ad = smem_u32(&sAl[(a_row + mi * 16) * SP + kk + a_koff]);
                ldm_x4(ad, al);
                #pragma unroll
                for (int nj = 0; nj < 4; nj++) {
                    mma_bf16(acc[mi][nj], ah, bh[nj]);
                    mma_bf16(acc[mi][nj], ah, bl[nj]);
                    mma_bf16(acc[mi][nj], al, bh[nj]);
                }
            }
        }

        if (more) {
            #pragma unroll
            for (int j = 0; j < 4; j++) {
                __align__(8) __nv_bfloat16 hb[4], lb[4];
                split2(av[j].x, hb[0], lb[0]); split2(av[j].y, hb[1], lb[1]);
                split2(av[j].z, hb[2], lb[2]); split2(av[j].w, hb[3], lb[3]);
                *(uint2*)(nAh + soff + j * 4) = *(uint2*)hb;
                *(uint2*)(nAl + soff + j * 4) = *(uint2*)lb;
            }
        }
        CP_WAIT0();
        __syncthreads();
    }

    const int gid = lane >> 2, tig = lane & 3;
    #pragma unroll
    for (int mi = 0; mi < 4; mi++) {
        int row = m0 + warp_m * 64 + mi * 16 + gid;
        #pragma unroll
        for (int nj = 0; nj < 4; nj++) {
            int col = n0 + warp_n * 32 + nj * 8 + tig * 2;
            *(float2*)&C[(size_t)row * ldc + col] =
                make_float2(acc[mi][nj][0], acc[mi][nj][1]);
            *(float2*)&C[(size_t)(row + 8) * ldc + col] =
                make_float2(acc[mi][nj][2], acc[mi][nj][3]);
        }
    }
}

// -------- pointwise: gate + ve, RoPE, RMSNorm*1.2, split-bf16 output --------
__global__ void __launch_bounds__(128) pointwise_kernel(
    const float* __restrict__ x,
    const float* __restrict__ ve,
    const float* __restrict__ cosb,
    const float* __restrict__ sinb,
    const float* __restrict__ Wg)
{
    const int bt   = blockIdx.x;
    const int b    = bt >> 11;
    const int t    = bt & (TT - 1);
    const int tid  = threadIdx.x;
    const int w    = tid >> 5;
    const int lane = tid & 31;

    float p = (lane < 12) ? x[bt * CC + lane] * Wg[lane * NKV + w] : 0.f;
    #pragma unroll
    for (int o = 16; o; o >>= 1) p += __shfl_xor_sync(0xffffffffu, p, o);
    const float gate = 3.f / (1.f + __expf(-p));

    const float c = cosb[t * 32 + lane];
    const float s = sinb[t * 32 + lane];
    const float* qkv = &g_qkv[bt * QKVN];

    for (int h = w; h < NH; h += 4) {
        float x1 = qkv[h * HD + lane];
        float x2 = qkv[h * HD + 32 + lane];
        float y1 =  x1 * c + x2 * s;
        float y2 = -x1 * s + x2 * c;
        float ss = y1 * y1 + y2 * y2;
        #pragma unroll
        for (int o = 16; o; o >>= 1) ss += __shfl_xor_sync(0xffffffffu, ss, o);
        float r = rsqrtf(ss * (1.f / 64.f) + 1e-6f) * 1.2f;
        size_t base = ((size_t)(b * NH + h) * TT + t) * HD;
        __nv_bfloat16 hi, lo;
        split2(y1 * r, hi, lo); g_Qh[base + lane]      = hi; g_Ql[base + lane]      = lo;
        split2(y2 * r, hi, lo); g_Qh[base + lane + 32] = hi; g_Ql[base + lane + 32] = lo;
    }
    {
        float x1 = qkv[1024 + w * HD + lane];
        float x2 = qkv[1024 + w * HD + 32 + lane];
        float y1 =  x1 * c + x2 * s;
        float y2 = -x1 * s + x2 * c;
        float ss = y1 * y1 + y2 * y2;
        #pragma unroll
        for (int o = 16; o; o >>= 1) ss += __shfl_xor_sync(0xffffffffu, ss, o);
        float r = rsqrtf(ss * (1.f / 64.f) + 1e-6f) * 1.2f;
        size_t base = ((size_t)(b * NKV + w) * TT + t) * HD;
        __nv_bfloat16 hi, lo;
        split2(y1 * r, hi, lo); g_Kh[base + lane]      = hi; g_Kl[base + lane]      = lo;
        split2(y2 * r, hi, lo); g_Kh[base + lane + 32] = hi; g_Kl[base + lane + 32] = lo;
    }
    {
        float v1 = qkv[1280 + w * HD + lane]      + gate * ve[bt * (NKV * HD) + w * HD + lane];
        float v2 = qkv[1280 + w * HD + 32 + lane] + gate * ve[bt * (NKV * HD) + w * HD + 32 + lane];
        size_t base = ((size_t)(b * NKV + w) * TT + t) * HD;
        __nv_bfloat16 hi, lo;
        split2(v1, hi, lo); g_Vh[base + lane]      = hi; g_Vl[base + lane]      = lo;
        split2(v2, hi, lo); g_Vh[base + lane + 32] = hi; g_Vl[base + lane + 32] = lo;
    }
}

// ==== tensor-core flash attention: 128 q-rows/CTA, 8 warps, dbuf K/V ========
#define AP 72
#define AQS (128 * AP)                   // Q array elems
#define AKS (64 * AP)                    // K/V tile array elems
#define ATT_SMEM ((2 * AQS + 8 * AKS) * 2)

__global__ void __launch_bounds__(256) attn_tc_kernel(const void* __restrict__ winptr)
{
    extern __shared__ __nv_bfloat16 smb[];
    __nv_bfloat16* sQh = smb;
    __nv_bfloat16* sQl = smb + AQS;

    const int q0 = blockIdx.x * 128;
    const int h  = blockIdx.y;
    const int b  = blockIdx.z;
    const int kh = h >> 2;

    const int tid = threadIdx.x, w = tid >> 5, lane = tid & 31;

    int  wi = *(const int*)winptr;
    float wf = *(const float*)winptr;
    const int W = (wi > 0 && wi < (1 << 20)) ? wi : (int)wf;

    const size_t kvbase = (size_t)(b * NKV + kh) * TT * HD;

    // K/V loader mapping: 256 threads, 64 rows x 4 quarters of 16 elems
    const int kr = tid >> 2, kq = tid & 3;
    const uint32_t ksoff = (uint32_t)(kr * AP + kq * 16) * 2;   // bytes

    int kbeg = q0 - W; if (kbeg < 0) kbeg = 0;
    const int kstart = (kbeg / 64) * 64;
    const int klast  = q0 + 64;                // last k-tile start

    auto issue_tile = [&](int k0, int bf) {
        const size_t g = kvbase + (size_t)(k0 + kr) * HD + kq * 16;
        uint32_t base = smem_u32(smb + 2 * AQS + bf * 4 * AKS) + ksoff;
        const __nv_bfloat16* srcs[4] = { g_Kh + g, g_Kl + g, g_Vh + g, g_Vl + g };
        #pragma unroll
        for (int a = 0; a < 4; a++) {
            cpa16(base + a * AKS * 2,      srcs[a]);
            cpa16(base + a * AKS * 2 + 16, srcs[a] + 8);
        }
    };

    // ---- Q tile (128 rows) -> smem ----
    {
        const int lr = tid >> 1, lhf = tid & 1;
        size_t gq = ((size_t)(b * NH + h) * TT + q0 + lr) * HD + lhf * 32;
        #pragma unroll
        for (int j = 0; j < 4; j++) {
            *(uint4*)&sQh[lr * AP + lhf * 32 + j * 8] = *(const uint4*)&g_Qh[gq + j * 8];
            *(uint4*)&sQl[lr * AP + lhf * 32 + j * 8] = *(const uint4*)&g_Ql[gq + j * 8];
        }
    }
    issue_tile(kstart, 0);
    CP_COMMIT();
    __syncthreads();

    // ---- Q fragments resident (warp w owns rows q0+16w..+15) ----
    uint32_t qh[4][4], ql[4][4];
    {
        const int qrow = w * 16 + (lane & 15);
        #pragma unroll
        for (int ks = 0; ks < 4; ks++) {
            int col = ks * 16 + ((lane & 16) ? 8 : 0);
            ldm_x4(smem_u32(&sQh[qrow * AP + col]), qh[ks]);
            ldm_x4(smem_u32(&sQl[qrow * AP + col]), ql[ks]);
        }
    }

    float o[8][4];
    #pragma unroll
    for (int d = 0; d < 8; d++)
        #pragma unroll
        for (int e = 0; e < 4; e++) o[d][e] = 0.f;
    float m_lo = -INFINITY, m_hi = -INFINITY, l_lo = 0.f, l_hi = 0.f;

    const int wmin = q0 + w * 16;           // warp's first row
    const int wmax = wmin + 15;             // warp's last row
    const int row_lo = wmin + (lane >> 2);
    const int row_hi = row_lo + 8;
    const int colb   = (lane & 3) * 2;

    int buf = 0;
    for (int k0 = kstart; k0 <= klast; k0 += 64) {
        CP_WAIT0();
        __syncthreads();
        if (k0 + 64 <= klast) {
            issue_tile(k0 + 64, buf ^ 1);
            CP_COMMIT();
        }

        // per-warp tile culling: fully above diagonal or fully below window
        const bool active = (k0 <= wmax) && (k0 + 63 >= wmin - W);
        if (active) {
            __nv_bfloat16* sKh = smb + 2 * AQS + buf * 4 * AKS;
            __nv_bfloat16* sKl = sKh + AKS;
            __nv_bfloat16* sVh = sKh + 2 * AKS;
            __nv_bfloat16* sVl = sKh + 3 * AKS;

            // ---- S = Q K^T ----
            float s[8][4];
            #pragma unroll
            for (int nj = 0; nj < 8; nj++)
                #pragma unroll
                for (int e = 0; e < 4; e++) s[nj][e] = 0.f;

            #pragma unroll
            for (int ks = 0; ks < 4; ks++) {
                #pragma unroll
                for (int nt = 0; nt < 4; nt++) {
                    int krow = nt * 16 + ((lane & 16) >> 1) + (lane & 7);
                    int col  = ks * 16 + ((lane & 8) ? 8 : 0);
                    uint32_t rh[4], rl[4];
                    ldm_x4(smem_u32(&sKh[krow * AP + col]), rh);
                    ldm_x4(smem_u32(&sKl[krow * AP + col]), rl);
                    #pragma unroll
                    for (int e = 0; e < 2; e++) {
                        uint32_t bhf[2] = { rh[e*2], rh[e*2+1] };
                        uint32_t blf[2] = { rl[e*2], rl[e*2+1] };
                        mma_bf16(s[nt*2+e], qh[ks], bhf);
                        mma_bf16(s[nt*2+e], ql[ks], bhf);
                        mma_bf16(s[nt*2+e], qh[ks], blf);
                    }
                }
            }

            // ---- mask + scale ----
            #pragma unroll
            for (int nj = 0; nj < 8; nj++) {
                #pragma unroll
                for (int e = 0; e < 4; e++) {
                    int col = k0 + nj * 8 + colb + (e & 1);
                    int row = (e < 2) ? row_lo : row_hi;
                    bool ok = (col <= row) && (row - col <= W);
                    s[nj][e] = ok ? s[nj][e] * 0.125f : -3e9f;
                }
            }

            // ---- online softmax ----
            float mx_lo = -INFINITY, mx_hi = -INFINITY;
            #pragma unroll
            for (int nj = 0; nj < 8; nj++) {
                mx_lo = fmaxf(mx_lo, fmaxf(s[nj][0], s[nj][1]));
                mx_hi = fmaxf(mx_hi, fmaxf(s[nj][2], s[nj][3]));
            }
            mx_lo = fmaxf(mx_lo, __shfl_xor_sync(0xffffffffu, mx_lo, 1));
            mx_lo = fmaxf(mx_lo, __shfl_xor_sync(0xffffffffu, mx_lo, 2));
            mx_hi = fmaxf(mx_hi, __shfl_xor_sync(0xffffffffu, mx_hi, 1));
            mx_hi = fmaxf(mx_hi, __shfl_xor_sync(0xffffffffu, mx_hi, 2));

            float mnew_lo = fmaxf(fmaxf(m_lo, mx_lo), -1e9f);
            float mnew_hi = fmaxf(fmaxf(m_hi, mx_hi), -1e9f);
            float sc_lo = __expf(m_lo - mnew_lo);
            float sc_hi = __expf(m_hi - mnew_hi);
            m_lo = mnew_lo; m_hi = mnew_hi;

            float sum_lo = 0.f, sum_hi = 0.f;
            #pragma unroll
            for (int nj = 0; nj < 8; nj++) {
                s[nj][0] = __expf(s[nj][0] - mnew_lo);
                s[nj][1] = __expf(s[nj][1] - mnew_lo);
                s[nj][2] = __expf(s[nj][2] - mnew_hi);
                s[nj][3] = __expf(s[nj][3] - mnew_hi);
                sum_lo += s[nj][0] + s[nj][1];
                sum_hi += s[nj][2] + s[nj][3];
            }
            sum_lo += __shfl_xor_sync(0xffffffffu, sum_lo, 1);
            sum_lo += __shfl_xor_sync(0xffffffffu, sum_lo, 2);
            sum_hi += __shfl_xor_sync(0xffffffffu, sum_hi, 1);
            sum_hi += __shfl_xor_sync(0xffffffffu, sum_hi, 2);
            l_lo = l_lo * sc_lo + sum_lo;
            l_hi = l_hi * sc_hi + sum_hi;

            #pragma unroll
            for (int d = 0; d < 8; d++) {
                o[d][0] *= sc_lo; o[d][1] *= sc_lo;
                o[d][2] *= sc_hi; o[d][3] *= sc_hi;
            }

            // ---- P -> bf16 fragments (hi + residual lo) ----
            uint32_t ph[4][4], pl[4][4];
            #pragma unroll
            for (int ks = 0; ks < 4; ks++) {
                #pragma unroll
                for (int e = 0; e < 2; e++) {
                    int nj = ks * 2 + e;
                    float p0 = s[nj][0], p1 = s[nj][1], p2 = s[nj][2], p3 = s[nj][3];
                    uint32_t h01 = packbf(p0, p1);
                    uint32_t h23 = packbf(p2, p3);
                    __nv_bfloat162 hb01 = *(__nv_bfloat162*)&h01;
                    __nv_bfloat162 hb23 = *(__nv_bfloat162*)&h23;
                    uint32_t l01 = packbf(p0 - __bfloat162float(hb01.x),
                                          p1 - __bfloat162float(hb01.y));
                    uint32_t l23 = packbf(p2 - __bfloat162float(hb23.x),
                                          p3 - __bfloat162float(hb23.y));
                    ph[ks][e*2]   = h01; ph[ks][e*2+1] = h23;
                    pl[ks][e*2]   = l01; pl[ks][e*2+1] = l23;
                }
            }

            // ---- O += P V ----
            #pragma unroll
            for (int ks = 0; ks < 4; ks++) {
                #pragma unroll
                for (int dt = 0; dt < 4; dt++) {
                    int vrow = ks * 16 + (lane & 15);
                    int vcol = dt * 16 + ((lane & 16) ? 8 : 0);
                    uint32_t rh[4], rl[4];
                    ldm_x4t(smem_u32(&sVh[vrow * AP + vcol]), rh);
                    ldm_x4t(smem_u32(&sVl[vrow * AP + vcol]), rl);
                    #pragma unroll
                    for (int e = 0; e < 2; e++) {
                        uint32_t bhf[2] = { rh[e*2], rh[e*2+1] };
                        uint32_t blf[2] = { rl[e*2], rl[e*2+1] };
                        mma_bf16(o[dt*2+e], ph[ks], bhf);
                        mma_bf16(o[dt*2+e], pl[ks], bhf);
                        mma_bf16(o[dt*2+e], ph[ks], blf);
                    }
                }
            }
        }
        buf ^= 1;
    }

    float li_lo = 1.f / l_lo, li_hi = 1.f / l_hi;
    #pragma unroll
    for (int d = 0; d < 8; d++) {
        int col = h * HD + d * 8 + colb;
        *(float2*)&g_Y[(size_t)(b * TT + row_lo) * CC + col] =
            make_float2(o[d][0] * li_lo, o[d][1] * li_lo);
        *(float2*)&g_Y[(size_t)(b * TT + row_hi) * CC + col] =
            make_float2(o[d][2] * li_hi, o[d][3] * li_hi);
    }
}

// ---------------------------------------------------------------------------
extern "C" void kernel_launch(void* const* d_in, const int* in_sizes, int n_in,
                              void* d_out, int out_size)
{
    const float* x    = (const float*)d_in[0];
    const float* ve   = (const float*)d_in[1];
    const float* cosb = (const float*)d_in[2];
    const float* sinb = (const float*)d_in[3];
    const float* Wq   = (const float*)d_in[4];
    const float* Wk   = (const float*)d_in[5];
    const float* Wv   = (const float*)d_in[6];
    const float* Wp   = (const float*)d_in[7];
    const float* Wg   = (const float*)d_in[8];
    const void*  win  = d_in[9];
    float* out = (float*)d_out;

    cudaFuncSetAttribute(attn_tc_kernel, cudaFuncAttributeMaxDynamicSharedMemorySize,
                         ATT_SMEM);
    cudaFuncSetAttribute(tc_gemm, cudaFuncAttributeMaxDynamicSharedMemorySize,
                         GEMM_SMEM);

    __nv_bfloat16 *wh, *wl, *ph, *pl;
    cudaGetSymbolAddress((void**)&wh, g_wh);
    cudaGetSymbolAddress((void**)&wl, g_wl);
    cudaGetSymbolAddress((void**)&ph, g_ph);
    cudaGetSymbolAddress((void**)&pl, g_pl);
    float *qkvp, *Yp;
    cudaGetSymbolAddress((void**)&qkvp, g_qkv);
    cudaGetSymbolAddress((void**)&Yp, g_Y);

    // weight transpose + split
    wtrans_kernel<<<dim3(32, 32), 256>>>(Wq, 1024, 0,    wh, wl);
    wtrans_kernel<<<dim3(8,  32), 256>>>(Wk, 256,  1024, wh, wl);
    wtrans_kernel<<<dim3(8,  32), 256>>>(Wv, 256,  1280, wh, wl);
    wtrans_kernel<<<dim3(32, 32), 256>>>(Wp, 1024, 0,    ph, pl);

    // qkv = x @ [Wq|Wk|Wv]
    tc_gemm<<<dim3(12, 32), 256, GEMM_SMEM>>>(x, wh, wl, qkvp, 1024, QKVN);

    pointwise_kernel<<<MTOT, 128>>>(x, ve, cosb, sinb, Wg);

    attn_tc_kernel<<<dim3(TT / 128, NH, BB), 256, ATT_SMEM>>>(win);

    // out = Y @ Wproj
    tc_gemm<<<dim3(8, 32), 256, GEMM_SMEM>>>(Yp, ph, pl, out, 1024, 1024);
}